// round 8
// baseline (speedup 1.0000x reference)
#include <cuda_runtime.h>
#include <math.h>

#define NUM_A 256
#define DIM 64
#define NSIG_TOTAL (32*64*64)
#define NBLOCKS (NSIG_TOTAL/64)      // 2048
#define NELEM 8388608

#define INV_LOG1P_MU 0.25433462858092786f
#define TAU_ARG  2e-3f
#define TAU_BIN  4e-3f
#define TAU_CHOL 1e-2f

// device-global scratch (no allocation allowed)
__device__ float  g_Dn[DIM*NUM_A];     // [c][a]
__device__ float  g_DnT[NUM_A*DIM];    // [a][c]
__device__ float  g_G[NUM_A*NUM_A];
__device__ double g_Dn64[DIM*NUM_A];
__device__ double g_G64[NUM_A*NUM_A];
__device__ float  g_partial[NBLOCKS];
__device__ float  g_fixloss[NSIG_TOTAL];
__device__ int    g_qcount;
__device__ int    g_queue[NSIG_TOTAL];

// ---------------- prep ----------------
__global__ void k_normalize(const float* __restrict__ dict){
    int a = threadIdx.x;
    if (a == 0) g_qcount = 0;
    float s = 0.f;  double s64 = 0.0;
    #pragma unroll
    for (int c = 0; c < DIM; ++c){
        float v = dict[c*NUM_A + a];
        s   = __fadd_rn(s, __fmul_rn(v, v));
        s64 = fma((double)v, (double)v, s64);
    }
    float  den   = fmaxf(__fsqrt_rn(s), 1e-10f);
    double den64 = fmax(sqrt(s64), 1e-10);
    #pragma unroll
    for (int c = 0; c < DIM; ++c){
        float v = __fdiv_rn(dict[c*NUM_A + a], den);
        g_Dn[c*NUM_A + a]  = v;
        g_DnT[a*DIM + c]   = v;
        g_Dn64[c*NUM_A + a] = (double)dict[c*NUM_A + a] / den64;
    }
}

__global__ void k_gram(){
    __shared__ float  di[DIM];
    __shared__ double di64[DIM];
    int i = blockIdx.x, j = threadIdx.x;
    if (j < DIM){ di[j] = g_DnT[i*DIM + j]; di64[j] = g_Dn64[j*NUM_A + i]; }
    __syncthreads();
    float s = 0.f;  double s64 = 0.0;
    #pragma unroll
    for (int c = 0; c < DIM; ++c){
        s   = __fmaf_rn(di[c], g_Dn[c*NUM_A + j], s);
        s64 = fma(di64[c], g_Dn64[c*NUM_A + j], s64);
    }
    g_G[i*NUM_A + j]   = s;
    g_G64[i*NUM_A + j] = s64;
}

// ---------------- mu-law (fp32, with boundary flag) ----------------
__device__ __forceinline__ float mu_law_q_flag(float v, int &flag){
    float cl = fminf(fmaxf(v, -3.0f), 3.0f);
    float c  = __fdiv_rn(cl, 3.0f);
    float enc = copysignf(__fmul_rn(log1pf(__fmul_rn(fabsf(c), 50.0f)), INV_LOG1P_MU), c);
    float scaled = __fmul_rn(__fadd_rn(enc, 1.0f), 7.5f);
    float fb = rintf(scaled);
    if (0.5f - fabsf(scaled - fb) < TAU_BIN) flag = 1;
    int b = (int)fb;
    b = max(0, min(15, b));
    float z = __fsub_rn(__fmul_rn((float)b, 2.0f/15.0f), 1.0f);
    float e = expm1f(__fdiv_rn(fabsf(z), INV_LOG1P_MU));
    return copysignf(__fmul_rn(__fdiv_rn(e, 50.0f), 3.0f), z);
}

// ---------------- main fused kernel (fp32 + uncertainty flags) ----------------
#define SM_DN   0
#define SM_DNT  16384
#define SM_X    32768
#define SM_H    36864
#define SM_R    53248
#define SM_FLOATS 57408
#define SM_BYTES (SM_FLOATS*4)

__global__ void __launch_bounds__(256,1) k_main(const float* __restrict__ z_e,
                                               float* __restrict__ out){
    extern __shared__ float S[];
    float* Dn_s  = S + SM_DN;
    float* DnT_s = S + SM_DNT;
    float* X_s   = S + SM_X;
    float* H_s   = S + SM_H;
    float* R_s   = S + SM_R;
    __shared__ int flag_s[64];
    __shared__ float red[8];

    const int t   = threadIdx.x;
    const int blk = blockIdx.x;
    const int b   = blk >> 6;
    const int p0  = (blk & 63) << 6;
    const float* src = z_e + (size_t)b*262144 + p0;
    float*       dst = out + (size_t)b*262144 + p0;

    {
        const float4* g0 = (const float4*)g_Dn;
        float4*       s0 = (float4*)Dn_s;
        #pragma unroll
        for (int k = 0; k < 16; ++k) s0[t + k*256] = g0[t + k*256];
        const float4* g1 = (const float4*)g_DnT;
        float4*       s1 = (float4*)DnT_s;
        #pragma unroll
        for (int k = 0; k < 16; ++k) s1[t + k*256] = g1[t + k*256];
    }
    {
        float4* xd = (float4*)X_s;
        #pragma unroll
        for (int k = 0; k < 4; ++k){
            int idx4 = t + k*256;
            int c = idx4 >> 4, p4 = idx4 & 15;
            xd[idx4] = *(const float4*)(src + c*4096 + p4*4);
        }
    }
    __syncthreads();

    const int tx = t & 31, ty = t >> 5;
    {   // GEMM: ascending-c fused FMA, 8x8 register tile
        float acc[8][8];
        #pragma unroll
        for (int i=0;i<8;++i)
            #pragma unroll
            for (int j=0;j<8;++j) acc[i][j] = 0.f;
        #pragma unroll 2
        for (int c = 0; c < 64; ++c){
            float4 b0 = *(float4*)&Dn_s[c*256 + tx*8];
            float4 b1 = *(float4*)&Dn_s[c*256 + tx*8 + 4];
            float4 a0 = *(float4*)&X_s[c*64 + ty*8];
            float4 a1 = *(float4*)&X_s[c*64 + ty*8 + 4];
            float av[8] = {a0.x,a0.y,a0.z,a0.w,a1.x,a1.y,a1.z,a1.w};
            float bv[8] = {b0.x,b0.y,b0.z,b0.w,b1.x,b1.y,b1.z,b1.w};
            #pragma unroll
            for (int si=0; si<8; ++si)
                #pragma unroll
                for (int aj=0; aj<8; ++aj)
                    acc[si][aj] = __fmaf_rn(av[si], bv[aj], acc[si][aj]);
        }
        #pragma unroll
        for (int si=0; si<8; ++si){
            *(float4*)&H_s[(ty*8+si)*256 + tx*8]     = make_float4(acc[si][0],acc[si][1],acc[si][2],acc[si][3]);
            *(float4*)&H_s[(ty*8+si)*256 + tx*8 + 4] = make_float4(acc[si][4],acc[si][5],acc[si][6],acc[si][7]);
        }
    }
    __syncthreads();

    const int lane = tx;
    for (int i = 0; i < 8; ++i){
        const int sig = ty*8 + i;
        float hb[8], h[8];
        #pragma unroll
        for (int j=0;j<8;++j){ hb[j] = H_s[sig*256 + j*32 + lane]; h[j]=hb[j]; }

        int   idxs[4];
        float L[4][4];
        float hbI[4];
        float xs[4];
        float gcol[4][8];
        int   flagged = 0;

        #pragma unroll
        for (int k = 0; k < 4; ++k){
            float best = -1.0f; int bi = 0;
            #pragma unroll
            for (int j=0;j<8;++j){
                int a = j*32 + lane;
                bool sel = false;
                #pragma unroll
                for (int q2=0;q2<4;++q2) if (q2<k && idxs[q2]==a) sel = true;
                float v = sel ? 0.0f : fabsf(h[j]);
                if (v > best || (v == best && a < bi)){ best = v; bi = a; }
            }
            #pragma unroll
            for (int off=16; off>0; off>>=1){
                float ov = __shfl_down_sync(0xffffffffu, best, off);
                int   oi = __shfl_down_sync(0xffffffffu, bi,   off);
                if (ov > best || (ov == best && oi < bi)){ best = ov; bi = oi; }
            }
            float bestv = __shfl_sync(0xffffffffu, best, 0);
            bi = __shfl_sync(0xffffffffu, bi, 0);
            idxs[k] = bi;

            // runner-up (excluding bi) for margin flag
            {
                float run = -1.0f;
                #pragma unroll
                for (int j=0;j<8;++j){
                    int a = j*32 + lane;
                    bool sel = (a == bi);
                    #pragma unroll
                    for (int q2=0;q2<4;++q2) if (q2<k && idxs[q2]==a) sel = true;
                    float v = sel ? 0.0f : fabsf(h[j]);
                    run = fmaxf(run, v);
                }
                #pragma unroll
                for (int off=16; off>0; off>>=1)
                    run = fmaxf(run, __shfl_down_sync(0xffffffffu, run, off));
                run = __shfl_sync(0xffffffffu, run, 0);
                if (bestv - run < TAU_ARG) flagged = 1;
            }

            #pragma unroll
            for (int j=0;j<8;++j) gcol[k][j] = g_G[bi*256 + j*32 + lane];

            if (k == 0){
                L[0][0] = 1.0f;
            } else {
                float w[4];
                #pragma unroll
                for (int r=0;r<4;++r){
                    if (r < k){
                        float v = g_G[idxs[r]*256 + bi];
                        #pragma unroll
                        for (int c2=0;c2<4;++c2) if (c2<r) v = __fmaf_rn(-L[r][c2], w[c2], v);
                        w[r] = __fdiv_rn(v, L[r][r]);
                    }
                }
                float ss = 0.f;
                #pragma unroll
                for (int c2=0;c2<4;++c2) if (c2<k) ss = __fadd_rn(ss, __fmul_rn(w[c2], w[c2]));
                #pragma unroll
                for (int c2=0;c2<4;++c2) if (c2<k) L[k][c2] = w[c2];
                float rem = __fsub_rn(1.0f, ss);
                if (rem < TAU_CHOL) flagged = 1;
                L[k][k] = __fsqrt_rn(fmaxf(rem, 1e-12f));
            }
            hbI[k] = H_s[sig*256 + bi];

            float y[4];
            #pragma unroll
            for (int r=0;r<4;++r) if (r<=k){
                float v = hbI[r];
                #pragma unroll
                for (int c2=0;c2<4;++c2) if (c2<r) v = __fmaf_rn(-L[r][c2], y[c2], v);
                y[r] = __fdiv_rn(v, L[r][r]);
            }
            #pragma unroll
            for (int r=3;r>=0;--r) if (r<=k){
                float v = y[r];
                #pragma unroll
                for (int c2=0;c2<4;++c2) if (c2>r && c2<=k) v = __fmaf_rn(-L[c2][r], xs[c2], v);
                xs[r] = __fdiv_rn(v, L[r][r]);
            }

            if (k < 3){
                #pragma unroll
                for (int j=0;j<8;++j){
                    float beta = 0.f;
                    #pragma unroll
                    for (int q2=0;q2<4;++q2)
                        if (q2<=k) beta = __fmaf_rn(xs[q2], gcol[q2][j], beta);
                    h[j] = __fsub_rn(hb[j], beta);
                }
            }
        }

        float q[4];
        #pragma unroll
        for (int k=0;k<4;++k) q[k] = mu_law_q_flag(xs[k], flagged);
        float r0 = 0.f, r1 = 0.f;
        #pragma unroll
        for (int k=0;k<4;++k){
            r0 = __fmaf_rn(q[k], DnT_s[idxs[k]*64 + lane],      r0);
            r1 = __fmaf_rn(q[k], DnT_s[idxs[k]*64 + lane + 32], r1);
        }
        R_s[lane*65 + sig]      = r0;
        R_s[(lane+32)*65 + sig] = r1;

        if (lane == 0){
            int gsig = blk*64 + sig;
            flag_s[sig] = flagged;
            g_fixloss[gsig] = 0.0f;
            if (flagged){
                int pos = atomicAdd(&g_qcount, 1);
                g_queue[pos] = gsig;
            }
        }
    }
    __syncthreads();

    // z_q write + loss (flagged signals excluded; fixed by k_fix)
    float lsum = 0.f;
    const int p  = t & 63;
    const int fl = flag_s[p];
    #pragma unroll
    for (int k = 0; k < 16; ++k){
        int idx = t + k*256;
        int c = idx >> 6;
        float x = X_s[idx];
        float r = R_s[c*65 + p];
        float d = __fsub_rn(r, x);
        if (fl){ dst[c*4096 + p] = x; }
        else   { dst[c*4096 + p] = __fadd_rn(x, d); lsum = __fmaf_rn(d, d, lsum); }
    }
    #pragma unroll
    for (int off=16; off>0; off>>=1) lsum += __shfl_down_sync(0xffffffffu, lsum, off);
    if (lane == 0) red[ty] = lsum;
    __syncthreads();
    if (t == 0){
        float s = 0.f;
        #pragma unroll
        for (int w2=0; w2<8; ++w2) s += red[w2];
        g_partial[blk] = s;
    }
}

// ---------------- fp64 exact re-solve for flagged signals ----------------
__global__ void k_fix(const float* __restrict__ z_e, float* __restrict__ out){
    __shared__ double xsh[8][64];
    const int lane = threadIdx.x & 31, wy = threadIdx.x >> 5;
    const int nwarps = gridDim.x * 8;
    const int w = blockIdx.x*8 + wy;
    const int cnt = g_qcount;
    const double INVD = 1.0 / log1p(50.0);

    for (int qi = w; qi < cnt; qi += nwarps){
        int gsig = g_queue[qi];
        int b = gsig >> 12, sp = gsig & 4095;
        const float* xp = z_e + (size_t)b*262144 + sp;
        float x0 = xp[(size_t)lane*4096], x1 = xp[(size_t)(lane+32)*4096];
        xsh[wy][lane] = (double)x0; xsh[wy][lane+32] = (double)x1;
        __syncwarp();

        double hb64[8], h64[8];
        #pragma unroll
        for (int j=0;j<8;++j){
            int a = j*32 + lane;
            double s = 0.0;
            #pragma unroll
            for (int c = 0; c < 64; ++c) s = fma(g_Dn64[c*NUM_A + a], xsh[wy][c], s);
            hb64[j] = s; h64[j] = s;
        }

        int idxs[4]; double L[4][4], xs[4], hbI[4];
        #pragma unroll
        for (int k = 0; k < 4; ++k){
            double best = -1.0; int bi = 0;
            #pragma unroll
            for (int j=0;j<8;++j){
                int a = j*32 + lane;
                bool sel = false;
                #pragma unroll
                for (int q2=0;q2<4;++q2) if (q2<k && idxs[q2]==a) sel = true;
                double v = sel ? 0.0 : fabs(h64[j]);
                if (v > best || (v == best && a < bi)){ best = v; bi = a; }
            }
            #pragma unroll
            for (int off=16; off>0; off>>=1){
                double ov = __shfl_down_sync(0xffffffffu, best, off);
                int    oi = __shfl_down_sync(0xffffffffu, bi,   off);
                if (ov > best || (ov == best && oi < bi)){ best = ov; bi = oi; }
            }
            bi = __shfl_sync(0xffffffffu, bi, 0);
            idxs[k] = bi;

            if (k == 0){
                L[0][0] = 1.0;
            } else {
                double wv[4];
                #pragma unroll
                for (int r=0;r<4;++r){
                    if (r < k){
                        double v = g_G64[idxs[r]*NUM_A + bi];
                        #pragma unroll
                        for (int c2=0;c2<4;++c2) if (c2<r) v = fma(-L[r][c2], wv[c2], v);
                        wv[r] = v / L[r][r];
                    }
                }
                double ss = 0.0;
                #pragma unroll
                for (int c2=0;c2<4;++c2) if (c2<k) ss = fma(wv[c2], wv[c2], ss);
                #pragma unroll
                for (int c2=0;c2<4;++c2) if (c2<k) L[k][c2] = wv[c2];
                L[k][k] = sqrt(fmax(1.0 - ss, 1e-12));
            }
            hbI[k] = __shfl_sync(0xffffffffu, hb64[bi >> 5], bi & 31);

            double y[4];
            #pragma unroll
            for (int r=0;r<4;++r) if (r<=k){
                double v = hbI[r];
                #pragma unroll
                for (int c2=0;c2<4;++c2) if (c2<r) v = fma(-L[r][c2], y[c2], v);
                y[r] = v / L[r][r];
            }
            #pragma unroll
            for (int r=3;r>=0;--r) if (r<=k){
                double v = y[r];
                #pragma unroll
                for (int c2=0;c2<4;++c2) if (c2>r && c2<=k) v = fma(-L[c2][r], xs[c2], v);
                xs[r] = v / L[r][r];
            }

            if (k < 3){
                #pragma unroll
                for (int j=0;j<8;++j){
                    int a = j*32 + lane;
                    double beta = 0.0;
                    #pragma unroll
                    for (int q2=0;q2<4;++q2)
                        if (q2<=k) beta = fma(xs[q2], g_G64[idxs[q2]*NUM_A + a], beta);
                    h64[j] = hb64[j] - beta;
                }
            }
        }

        // true-bin quantize + same fp32 recon formula as k_main
        float r0 = 0.f, r1 = 0.f;
        #pragma unroll
        for (int k=0;k<4;++k){
            double v = xs[k];
            double cl = fmin(fmax(v, -3.0), 3.0);
            double c  = cl / 3.0;
            double enc = copysign(log1p(fabs(c)*50.0) * INVD, c);
            double scaled = (enc + 1.0) * 7.5;
            int bq = (int)rint(scaled);
            bq = max(0, min(15, bq));
            double z = (double)bq * (2.0/15.0) - 1.0;
            float qk = (float)copysign(expm1(fabs(z)/INVD)/50.0*3.0, z);
            r0 = __fmaf_rn(qk, g_DnT[idxs[k]*64 + lane],      r0);
            r1 = __fmaf_rn(qk, g_DnT[idxs[k]*64 + lane + 32], r1);
        }
        float d0 = __fsub_rn(r0, x0), d1 = __fsub_rn(r1, x1);
        out[(size_t)b*262144 + (size_t)lane*4096 + sp]      = __fadd_rn(x0, d0);
        out[(size_t)b*262144 + (size_t)(lane+32)*4096 + sp] = __fadd_rn(x1, d1);
        float ls = __fmaf_rn(d0, d0, __fmul_rn(d1, d1));
        #pragma unroll
        for (int off=16; off>0; off>>=1) ls += __shfl_down_sync(0xffffffffu, ls, off);
        if (lane == 0) g_fixloss[gsig] = ls;
        __syncwarp();
    }
}

// ---------------- finalize ----------------
__global__ void k_final(float* __restrict__ out, int out_size){
    __shared__ float red[256];
    float s = 0.f;
    for (int i = threadIdx.x; i < NBLOCKS; i += 256) s += g_partial[i];
    for (int i = threadIdx.x; i < NSIG_TOTAL; i += 256) s += g_fixloss[i];
    red[threadIdx.x] = s;
    __syncthreads();
    for (int o = 128; o > 0; o >>= 1){
        if (threadIdx.x < o) red[threadIdx.x] += red[threadIdx.x + o];
        __syncthreads();
    }
    if (threadIdx.x == 0 && out_size > NELEM)
        out[NELEM] = 1.25f * red[0] / (float)NELEM;
}

// ---------------- launch ----------------
extern "C" void kernel_launch(void* const* d_in, const int* in_sizes, int n_in,
                              void* d_out, int out_size){
    const float* z_e  = (const float*)d_in[0];
    const float* dict = (const float*)d_in[1];
    float* out = (float*)d_out;

    cudaFuncSetAttribute(k_main, cudaFuncAttributeMaxDynamicSharedMemorySize, SM_BYTES);

    k_normalize<<<1, 256>>>(dict);
    k_gram<<<256, 256>>>();
    k_main<<<NBLOCKS, 256, SM_BYTES>>>(z_e, out);
    k_fix<<<256, 256>>>(z_e, out);
    k_final<<<1, 256>>>(out, out_size);
}

// round 9
// speedup vs baseline: 1.8399x; 1.8399x over previous
#include <cuda_runtime.h>
#include <math.h>

#define NUM_A 256
#define DIM 64
#define NSIG_TOTAL (32*64*64)
#define NBLOCKS (NSIG_TOTAL/64)      // 2048
#define NELEM 8388608

#define INV_LOG1P_MU 0.25433462858092786f
#define TAU_ARG  3e-4f
#define TAU_BIN  1.5e-3f
#define TAU_CHOL 1e-2f

// device-global scratch (no allocation allowed)
__device__ float  g_Dn[DIM*NUM_A];     // [c][a]
__device__ float  g_DnT[NUM_A*DIM];    // [a][c]
__device__ float  g_G[NUM_A*NUM_A];
__device__ double g_Dn64[DIM*NUM_A];
__device__ double g_G64[NUM_A*NUM_A];
__device__ float  g_partial[NBLOCKS];
__device__ float  g_fixloss[NSIG_TOTAL];
__device__ int    g_qcount;
__device__ int    g_queue[NSIG_TOTAL];

// ---------------- prep ----------------
__global__ void k_normalize(const float* __restrict__ dict){
    int a = threadIdx.x;
    if (a == 0) g_qcount = 0;
    float s = 0.f;  double s64 = 0.0;
    #pragma unroll
    for (int c = 0; c < DIM; ++c){
        float v = dict[c*NUM_A + a];
        s   = __fadd_rn(s, __fmul_rn(v, v));
        s64 = fma((double)v, (double)v, s64);
    }
    float  den   = fmaxf(__fsqrt_rn(s), 1e-10f);
    double den64 = fmax(sqrt(s64), 1e-10);
    #pragma unroll
    for (int c = 0; c < DIM; ++c){
        float v = __fdiv_rn(dict[c*NUM_A + a], den);
        g_Dn[c*NUM_A + a]  = v;
        g_DnT[a*DIM + c]   = v;
        g_Dn64[c*NUM_A + a] = (double)dict[c*NUM_A + a] / den64;
    }
}

__global__ void k_gram(){
    __shared__ float  di[DIM];
    __shared__ double di64[DIM];
    int i = blockIdx.x, j = threadIdx.x;
    if (j < DIM){ di[j] = g_DnT[i*DIM + j]; di64[j] = g_Dn64[j*NUM_A + i]; }
    __syncthreads();
    float s = 0.f;  double s64 = 0.0;
    #pragma unroll
    for (int c = 0; c < DIM; ++c){
        s   = __fmaf_rn(di[c], g_Dn[c*NUM_A + j], s);
        s64 = fma(di64[c], g_Dn64[c*NUM_A + j], s64);
    }
    g_G[i*NUM_A + j]   = s;
    g_G64[i*NUM_A + j] = s64;
}

// ---------------- mu-law (fp32, with boundary flag) ----------------
__device__ __forceinline__ float mu_law_q_flag(float v, int &flag){
    float cl = fminf(fmaxf(v, -3.0f), 3.0f);
    float c  = __fdiv_rn(cl, 3.0f);
    float enc = copysignf(__fmul_rn(log1pf(__fmul_rn(fabsf(c), 50.0f)), INV_LOG1P_MU), c);
    float scaled = __fmul_rn(__fadd_rn(enc, 1.0f), 7.5f);
    float fb = rintf(scaled);
    if (0.5f - fabsf(scaled - fb) < TAU_BIN) flag = 1;
    int b = (int)fb;
    b = max(0, min(15, b));
    float z = __fsub_rn(__fmul_rn((float)b, 2.0f/15.0f), 1.0f);
    float e = expm1f(__fdiv_rn(fabsf(z), INV_LOG1P_MU));
    return copysignf(__fmul_rn(__fdiv_rn(e, 50.0f), 3.0f), z);
}

// ---------------- main fused kernel (fp32 + uncertainty flags) ----------------
#define SM_DN   0
#define SM_DNT  16384
#define SM_X    32768
#define SM_H    36864
#define SM_R    53248
#define SM_FLOATS 57408
#define SM_BYTES (SM_FLOATS*4)

__global__ void __launch_bounds__(256,1) k_main(const float* __restrict__ z_e,
                                               float* __restrict__ out){
    extern __shared__ float S[];
    float* Dn_s  = S + SM_DN;
    float* DnT_s = S + SM_DNT;
    float* X_s   = S + SM_X;
    float* H_s   = S + SM_H;
    float* R_s   = S + SM_R;
    __shared__ int flag_s[64];
    __shared__ float red[8];

    const int t   = threadIdx.x;
    const int blk = blockIdx.x;
    const int b   = blk >> 6;
    const int p0  = (blk & 63) << 6;
    const float* src = z_e + (size_t)b*262144 + p0;
    float*       dst = out + (size_t)b*262144 + p0;

    {
        const float4* g0 = (const float4*)g_Dn;
        float4*       s0 = (float4*)Dn_s;
        #pragma unroll
        for (int k = 0; k < 16; ++k) s0[t + k*256] = g0[t + k*256];
        const float4* g1 = (const float4*)g_DnT;
        float4*       s1 = (float4*)DnT_s;
        #pragma unroll
        for (int k = 0; k < 16; ++k) s1[t + k*256] = g1[t + k*256];
    }
    {
        float4* xd = (float4*)X_s;
        #pragma unroll
        for (int k = 0; k < 4; ++k){
            int idx4 = t + k*256;
            int c = idx4 >> 4, p4 = idx4 & 15;
            xd[idx4] = *(const float4*)(src + c*4096 + p4*4);
        }
    }
    __syncthreads();

    const int tx = t & 31, ty = t >> 5;
    {   // GEMM: ascending-c fused FMA, 8x8 register tile
        float acc[8][8];
        #pragma unroll
        for (int i=0;i<8;++i)
            #pragma unroll
            for (int j=0;j<8;++j) acc[i][j] = 0.f;
        #pragma unroll 2
        for (int c = 0; c < 64; ++c){
            float4 b0 = *(float4*)&Dn_s[c*256 + tx*8];
            float4 b1 = *(float4*)&Dn_s[c*256 + tx*8 + 4];
            float4 a0 = *(float4*)&X_s[c*64 + ty*8];
            float4 a1 = *(float4*)&X_s[c*64 + ty*8 + 4];
            float av[8] = {a0.x,a0.y,a0.z,a0.w,a1.x,a1.y,a1.z,a1.w};
            float bv[8] = {b0.x,b0.y,b0.z,b0.w,b1.x,b1.y,b1.z,b1.w};
            #pragma unroll
            for (int si=0; si<8; ++si)
                #pragma unroll
                for (int aj=0; aj<8; ++aj)
                    acc[si][aj] = __fmaf_rn(av[si], bv[aj], acc[si][aj]);
        }
        #pragma unroll
        for (int si=0; si<8; ++si){
            *(float4*)&H_s[(ty*8+si)*256 + tx*8]     = make_float4(acc[si][0],acc[si][1],acc[si][2],acc[si][3]);
            *(float4*)&H_s[(ty*8+si)*256 + tx*8 + 4] = make_float4(acc[si][4],acc[si][5],acc[si][6],acc[si][7]);
        }
    }
    __syncthreads();

    const int lane = tx;
    for (int i = 0; i < 8; ++i){
        const int sig = ty*8 + i;
        float hb[8], h[8];
        #pragma unroll
        for (int j=0;j<8;++j){ hb[j] = H_s[sig*256 + j*32 + lane]; h[j]=hb[j]; }

        int   idxs[4];
        float L[4][4];
        float hbI[4];
        float xs[4];
        float gcol[4][8];
        int   flagged = 0;

        #pragma unroll
        for (int k = 0; k < 4; ++k){
            // single-pass top-2 masked argmax of |h|
            float b1v = -1.0f, b2v = -1.0f; int b1i = 0;
            #pragma unroll
            for (int j=0;j<8;++j){
                int a = j*32 + lane;
                bool sel = false;
                #pragma unroll
                for (int q2=0;q2<4;++q2) if (q2<k && idxs[q2]==a) sel = true;
                float v = sel ? 0.0f : fabsf(h[j]);
                if (v > b1v || (v == b1v && a < b1i)){ b2v = b1v; b1v = v; b1i = a; }
                else if (v > b2v) b2v = v;
            }
            #pragma unroll
            for (int off=16; off>0; off>>=1){
                float ov1 = __shfl_down_sync(0xffffffffu, b1v, off);
                int   oi1 = __shfl_down_sync(0xffffffffu, b1i, off);
                float ov2 = __shfl_down_sync(0xffffffffu, b2v, off);
                if (ov1 > b1v || (ov1 == b1v && oi1 < b1i)){
                    b2v = fmaxf(b1v, ov2); b1v = ov1; b1i = oi1;
                } else {
                    b2v = fmaxf(b2v, ov1);
                }
            }
            float bestv = __shfl_sync(0xffffffffu, b1v, 0);
            float runv  = __shfl_sync(0xffffffffu, b2v, 0);
            int bi      = __shfl_sync(0xffffffffu, b1i, 0);
            idxs[k] = bi;
            if (bestv - runv < TAU_ARG) flagged = 1;

            #pragma unroll
            for (int j=0;j<8;++j) gcol[k][j] = g_G[bi*256 + j*32 + lane];

            if (k == 0){
                L[0][0] = 1.0f;
            } else {
                float w[4];
                #pragma unroll
                for (int r=0;r<4;++r){
                    if (r < k){
                        float v = g_G[idxs[r]*256 + bi];
                        #pragma unroll
                        for (int c2=0;c2<4;++c2) if (c2<r) v = __fmaf_rn(-L[r][c2], w[c2], v);
                        w[r] = __fdiv_rn(v, L[r][r]);
                    }
                }
                float ss = 0.f;
                #pragma unroll
                for (int c2=0;c2<4;++c2) if (c2<k) ss = __fadd_rn(ss, __fmul_rn(w[c2], w[c2]));
                #pragma unroll
                for (int c2=0;c2<4;++c2) if (c2<k) L[k][c2] = w[c2];
                float rem = __fsub_rn(1.0f, ss);
                if (rem < TAU_CHOL) flagged = 1;
                L[k][k] = __fsqrt_rn(fmaxf(rem, 1e-12f));
            }
            hbI[k] = H_s[sig*256 + bi];

            float y[4];
            #pragma unroll
            for (int r=0;r<4;++r) if (r<=k){
                float v = hbI[r];
                #pragma unroll
                for (int c2=0;c2<4;++c2) if (c2<r) v = __fmaf_rn(-L[r][c2], y[c2], v);
                y[r] = __fdiv_rn(v, L[r][r]);
            }
            #pragma unroll
            for (int r=3;r>=0;--r) if (r<=k){
                float v = y[r];
                #pragma unroll
                for (int c2=0;c2<4;++c2) if (c2>r && c2<=k) v = __fmaf_rn(-L[c2][r], xs[c2], v);
                xs[r] = __fdiv_rn(v, L[r][r]);
            }

            if (k < 3){
                #pragma unroll
                for (int j=0;j<8;++j){
                    float beta = 0.f;
                    #pragma unroll
                    for (int q2=0;q2<4;++q2)
                        if (q2<=k) beta = __fmaf_rn(xs[q2], gcol[q2][j], beta);
                    h[j] = __fsub_rn(hb[j], beta);
                }
            }
        }

        float q[4];
        #pragma unroll
        for (int k=0;k<4;++k) q[k] = mu_law_q_flag(xs[k], flagged);
        float r0 = 0.f, r1 = 0.f;
        #pragma unroll
        for (int k=0;k<4;++k){
            r0 = __fmaf_rn(q[k], DnT_s[idxs[k]*64 + lane],      r0);
            r1 = __fmaf_rn(q[k], DnT_s[idxs[k]*64 + lane + 32], r1);
        }
        R_s[lane*65 + sig]      = r0;
        R_s[(lane+32)*65 + sig] = r1;

        if (lane == 0){
            int gsig = blk*64 + sig;
            flag_s[sig] = flagged;
            g_fixloss[gsig] = 0.0f;
            if (flagged){
                int pos = atomicAdd(&g_qcount, 1);
                g_queue[pos] = gsig;
            }
        }
    }
    __syncthreads();

    // z_q write + loss (flagged signals excluded; fixed by k_fix)
    float lsum = 0.f;
    const int p  = t & 63;
    const int fl = flag_s[p];
    #pragma unroll
    for (int k = 0; k < 16; ++k){
        int idx = t + k*256;
        int c = idx >> 6;
        float x = X_s[idx];
        float r = R_s[c*65 + p];
        float d = __fsub_rn(r, x);
        if (fl){ dst[c*4096 + p] = x; }
        else   { dst[c*4096 + p] = __fadd_rn(x, d); lsum = __fmaf_rn(d, d, lsum); }
    }
    #pragma unroll
    for (int off=16; off>0; off>>=1) lsum += __shfl_down_sync(0xffffffffu, lsum, off);
    if (lane == 0) red[ty] = lsum;
    __syncthreads();
    if (t == 0){
        float s = 0.f;
        #pragma unroll
        for (int w2=0; w2<8; ++w2) s += red[w2];
        g_partial[blk] = s;
    }
}

// ---------------- fp64 exact re-solve for flagged signals ----------------
__global__ void __launch_bounds__(256) k_fix(const float* __restrict__ z_e,
                                             float* __restrict__ out){
    __shared__ double xsh[8][64];
    const int lane = threadIdx.x & 31, wy = threadIdx.x >> 5;
    const int nwarps = gridDim.x * 8;
    const int w = blockIdx.x*8 + wy;
    const int cnt = g_qcount;
    const double INVD = 1.0 / log1p(50.0);

    for (int qi = w; qi < cnt; qi += nwarps){
        int gsig = g_queue[qi];
        int b = gsig >> 12, sp = gsig & 4095;
        const float* xp = z_e + (size_t)b*262144 + sp;
        float x0 = xp[(size_t)lane*4096], x1 = xp[(size_t)(lane+32)*4096];
        xsh[wy][lane] = (double)x0; xsh[wy][lane+32] = (double)x1;
        __syncwarp();

        // fp64 H, 2-way split accumulation (halves dependency-chain latency;
        // ulp-level change to truth — decision-safe)
        double hb64[8], h64[8];
        #pragma unroll
        for (int j=0;j<8;++j){
            int a = j*32 + lane;
            double s0 = 0.0, s1 = 0.0;
            #pragma unroll
            for (int c = 0; c < 32; ++c){
                s0 = fma(g_Dn64[(2*c  )*NUM_A + a], xsh[wy][2*c  ], s0);
                s1 = fma(g_Dn64[(2*c+1)*NUM_A + a], xsh[wy][2*c+1], s1);
            }
            hb64[j] = s0 + s1; h64[j] = hb64[j];
        }

        int idxs[4]; double L[4][4], xs[4], hbI[4];
        #pragma unroll
        for (int k = 0; k < 4; ++k){
            double best = -1.0; int bi = 0;
            #pragma unroll
            for (int j=0;j<8;++j){
                int a = j*32 + lane;
                bool sel = false;
                #pragma unroll
                for (int q2=0;q2<4;++q2) if (q2<k && idxs[q2]==a) sel = true;
                double v = sel ? 0.0 : fabs(h64[j]);
                if (v > best || (v == best && a < bi)){ best = v; bi = a; }
            }
            #pragma unroll
            for (int off=16; off>0; off>>=1){
                double ov = __shfl_down_sync(0xffffffffu, best, off);
                int    oi = __shfl_down_sync(0xffffffffu, bi,   off);
                if (ov > best || (ov == best && oi < bi)){ best = ov; bi = oi; }
            }
            bi = __shfl_sync(0xffffffffu, bi, 0);
            idxs[k] = bi;

            if (k == 0){
                L[0][0] = 1.0;
            } else {
                double wv[4];
                #pragma unroll
                for (int r=0;r<4;++r){
                    if (r < k){
                        double v = g_G64[idxs[r]*NUM_A + bi];
                        #pragma unroll
                        for (int c2=0;c2<4;++c2) if (c2<r) v = fma(-L[r][c2], wv[c2], v);
                        wv[r] = v / L[r][r];
                    }
                }
                double ss = 0.0;
                #pragma unroll
                for (int c2=0;c2<4;++c2) if (c2<k) ss = fma(wv[c2], wv[c2], ss);
                #pragma unroll
                for (int c2=0;c2<4;++c2) if (c2<k) L[k][c2] = wv[c2];
                L[k][k] = sqrt(fmax(1.0 - ss, 1e-12));
            }
            // broadcast hb64 at atom bi without dynamic register indexing
            {
                int jsel = bi >> 5;
                double v = hb64[0];
                #pragma unroll
                for (int j=1;j<8;++j) if (jsel == j) v = hb64[j];
                hbI[k] = __shfl_sync(0xffffffffu, v, bi & 31);
            }

            double y[4];
            #pragma unroll
            for (int r=0;r<4;++r) if (r<=k){
                double v = hbI[r];
                #pragma unroll
                for (int c2=0;c2<4;++c2) if (c2<r) v = fma(-L[r][c2], y[c2], v);
                y[r] = v / L[r][r];
            }
            #pragma unroll
            for (int r=3;r>=0;--r) if (r<=k){
                double v = y[r];
                #pragma unroll
                for (int c2=0;c2<4;++c2) if (c2>r && c2<=k) v = fma(-L[c2][r], xs[c2], v);
                xs[r] = v / L[r][r];
            }

            if (k < 3){
                #pragma unroll
                for (int j=0;j<8;++j){
                    int a = j*32 + lane;
                    double beta = 0.0;
                    #pragma unroll
                    for (int q2=0;q2<4;++q2)
                        if (q2<=k) beta = fma(xs[q2], g_G64[idxs[q2]*NUM_A + a], beta);
                    h64[j] = hb64[j] - beta;
                }
            }
        }

        // true-bin quantize + same fp32 recon formula as k_main
        float r0 = 0.f, r1 = 0.f;
        #pragma unroll
        for (int k=0;k<4;++k){
            double v = xs[k];
            double cl = fmin(fmax(v, -3.0), 3.0);
            double c  = cl / 3.0;
            double enc = copysign(log1p(fabs(c)*50.0) * INVD, c);
            double scaled = (enc + 1.0) * 7.5;
            int bq = (int)rint(scaled);
            bq = max(0, min(15, bq));
            double z = (double)bq * (2.0/15.0) - 1.0;
            float qk = (float)copysign(expm1(fabs(z)/INVD)/50.0*3.0, z);
            r0 = __fmaf_rn(qk, g_DnT[idxs[k]*64 + lane],      r0);
            r1 = __fmaf_rn(qk, g_DnT[idxs[k]*64 + lane + 32], r1);
        }
        float d0 = __fsub_rn(r0, x0), d1 = __fsub_rn(r1, x1);
        out[(size_t)b*262144 + (size_t)lane*4096 + sp]      = __fadd_rn(x0, d0);
        out[(size_t)b*262144 + (size_t)(lane+32)*4096 + sp] = __fadd_rn(x1, d1);
        float ls = __fmaf_rn(d0, d0, __fmul_rn(d1, d1));
        #pragma unroll
        for (int off=16; off>0; off>>=1) ls += __shfl_down_sync(0xffffffffu, ls, off);
        if (lane == 0) g_fixloss[gsig] = ls;
        __syncwarp();
    }
}

// ---------------- finalize ----------------
__global__ void k_final(float* __restrict__ out, int out_size){
    __shared__ float red[256];
    float s = 0.f;
    for (int i = threadIdx.x; i < NBLOCKS; i += 256) s += g_partial[i];
    for (int i = threadIdx.x; i < NSIG_TOTAL; i += 256) s += g_fixloss[i];
    red[threadIdx.x] = s;
    __syncthreads();
    for (int o = 128; o > 0; o >>= 1){
        if (threadIdx.x < o) red[threadIdx.x] += red[threadIdx.x + o];
        __syncthreads();
    }
    if (threadIdx.x == 0 && out_size > NELEM)
        out[NELEM] = 1.25f * red[0] / (float)NELEM;
}

// ---------------- launch ----------------
extern "C" void kernel_launch(void* const* d_in, const int* in_sizes, int n_in,
                              void* d_out, int out_size){
    const float* z_e  = (const float*)d_in[0];
    const float* dict = (const float*)d_in[1];
    float* out = (float*)d_out;

    cudaFuncSetAttribute(k_main, cudaFuncAttributeMaxDynamicSharedMemorySize, SM_BYTES);

    k_normalize<<<1, 256>>>(dict);
    k_gram<<<256, 256>>>();
    k_main<<<NBLOCKS, 256, SM_BYTES>>>(z_e, out);
    k_fix<<<296, 256>>>(z_e, out);
    k_final<<<1, 256>>>(out, out_size);
}

// round 10
// speedup vs baseline: 2.5911x; 1.4082x over previous
#include <cuda_runtime.h>
#include <math.h>

#define NUM_A 256
#define DIM 64
#define NSIG_TOTAL (32*64*64)
#define NBLOCKS (NSIG_TOTAL/64)      // 2048
#define NELEM 8388608

#define INV_LOG1P_MU 0.25433462858092786f
#define TAU_ARG  1e-4f
#define TAU_BIN  6e-4f
#define TAU_CHOL 1e-2f

// device-global scratch (no allocation allowed)
__device__ float  g_Dn[DIM*NUM_A];     // [c][a]
__device__ float  g_DnT[NUM_A*DIM];    // [a][c]
__device__ float  g_G[NUM_A*NUM_A];
__device__ double g_Dn64[DIM*NUM_A];
__device__ double g_G64[NUM_A*NUM_A];
__device__ float  g_partial[NBLOCKS];
__device__ float  g_partial2[512];
__device__ float  g_fixloss[NSIG_TOTAL];
__device__ int    g_qcount;
__device__ int    g_queue[NSIG_TOTAL];

// ---------------- prep ----------------
__global__ void k_normalize(const float* __restrict__ dict){
    int a = threadIdx.x;
    if (a == 0) g_qcount = 0;
    float s = 0.f;  double s64 = 0.0;
    #pragma unroll
    for (int c = 0; c < DIM; ++c){
        float v = dict[c*NUM_A + a];
        s   = __fadd_rn(s, __fmul_rn(v, v));
        s64 = fma((double)v, (double)v, s64);
    }
    float  den   = fmaxf(__fsqrt_rn(s), 1e-10f);
    double den64 = fmax(sqrt(s64), 1e-10);
    #pragma unroll
    for (int c = 0; c < DIM; ++c){
        float v = __fdiv_rn(dict[c*NUM_A + a], den);
        g_Dn[c*NUM_A + a]  = v;
        g_DnT[a*DIM + c]   = v;
        g_Dn64[c*NUM_A + a] = (double)dict[c*NUM_A + a] / den64;
    }
}

__global__ void k_gram(){
    __shared__ float  di[DIM];
    __shared__ double di64[DIM];
    int i = blockIdx.x, j = threadIdx.x;
    if (j < DIM){ di[j] = g_DnT[i*DIM + j]; di64[j] = g_Dn64[j*NUM_A + i]; }
    __syncthreads();
    float s = 0.f;  double s64 = 0.0;
    #pragma unroll
    for (int c = 0; c < DIM; ++c){
        s   = __fmaf_rn(di[c], g_Dn[c*NUM_A + j], s);
        s64 = fma(di64[c], g_Dn64[c*NUM_A + j], s64);
    }
    g_G[i*NUM_A + j]   = s;
    g_G64[i*NUM_A + j] = s64;
}

// ---------------- mu-law (fp32, with boundary flag) ----------------
__device__ __forceinline__ float mu_law_q_flag(float v, int &flag){
    float cl = fminf(fmaxf(v, -3.0f), 3.0f);
    float c  = __fdiv_rn(cl, 3.0f);
    float enc = copysignf(__fmul_rn(log1pf(__fmul_rn(fabsf(c), 50.0f)), INV_LOG1P_MU), c);
    float scaled = __fmul_rn(__fadd_rn(enc, 1.0f), 7.5f);
    float fb = rintf(scaled);
    if (0.5f - fabsf(scaled - fb) < TAU_BIN) flag = 1;
    int b = (int)fb;
    b = max(0, min(15, b));
    float z = __fsub_rn(__fmul_rn((float)b, 2.0f/15.0f), 1.0f);
    float e = expm1f(__fdiv_rn(fabsf(z), INV_LOG1P_MU));
    return copysignf(__fmul_rn(__fdiv_rn(e, 50.0f), 3.0f), z);
}

// ---------------- main fused kernel: 512 thr, H in registers ----------------
// smem floats: Dn_s [64][256] @0 (16384), X_s [64][64] @16384 (4096),
//              R_s [64][65] @20480 (4160).  Total 24640 floats = 98560 B.
#define SM_DN 0
#define SM_X  16384
#define SM_R  20480
#define SM_FLOATS 24640
#define SM_BYTES (SM_FLOATS*4)

__global__ void __launch_bounds__(512,1) k_main(const float* __restrict__ z_e,
                                               float* __restrict__ out){
    extern __shared__ float S[];
    float* Dn_s = S + SM_DN;
    float* X_s  = S + SM_X;
    float* R_s  = S + SM_R;
    __shared__ int flag_s[64];
    __shared__ float red[16];

    const int t    = threadIdx.x;
    const int w    = t >> 5;          // warp 0..15, handles signals w*4..w*4+3
    const int lane = t & 31;
    const int blk  = blockIdx.x;
    const int b    = blk >> 6;
    const int p0   = (blk & 63) << 6;
    const float* src = z_e + (size_t)b*262144 + p0;
    float*       dst = out + (size_t)b*262144 + p0;

    // --- load Dn tile (4096 float4 over 512 threads) ---
    {
        const float4* g0 = (const float4*)g_Dn;
        float4*       s0 = (float4*)Dn_s;
        #pragma unroll
        for (int k = 0; k < 8; ++k) s0[t + k*512] = g0[t + k*512];
    }
    // --- load X tile: X_s[c][p] ---
    {
        float4* xd = (float4*)X_s;
        #pragma unroll
        for (int k = 0; k < 2; ++k){
            int idx4 = t + k*512;
            int c = idx4 >> 4, p4 = idx4 & 15;
            xd[idx4] = *(const float4*)(src + c*4096 + p4*4);
        }
    }
    __syncthreads();

    // --- GEMM into registers: acc[si][j] = H[w*4+si][j*32+lane]
    //     ascending-c single-accumulator fused FMA (bit-identical to R9 H) ---
    float acc[4][8];
    #pragma unroll
    for (int si=0; si<4; ++si)
        #pragma unroll
        for (int j=0; j<8; ++j) acc[si][j] = 0.f;
    #pragma unroll 2
    for (int c = 0; c < 64; ++c){
        float dn[8];
        #pragma unroll
        for (int j=0; j<8; ++j) dn[j] = Dn_s[c*256 + j*32 + lane];
        float xv[4];
        #pragma unroll
        for (int si=0; si<4; ++si) xv[si] = X_s[c*64 + w*4 + si];
        #pragma unroll
        for (int si=0; si<4; ++si)
            #pragma unroll
            for (int j=0; j<8; ++j)
                acc[si][j] = __fmaf_rn(xv[si], dn[j], acc[si][j]);
    }

    // --- OMP per signal (4 per warp), H in registers ---
    for (int i = 0; i < 4; ++i){
        const int sig = w*4 + i;
        float hb[8], h[8];
        #pragma unroll
        for (int j=0;j<8;++j){ hb[j] = acc[i][j]; h[j] = hb[j]; }

        int   idxs[4];
        float L[4][4];
        float hbI[4];
        float xs[4];
        float gcol[4][8];
        int   flagged = 0;

        #pragma unroll
        for (int k = 0; k < 4; ++k){
            // single-pass top-2 masked argmax of |h|
            float b1v = -1.0f, b2v = -1.0f; int b1i = 0;
            #pragma unroll
            for (int j=0;j<8;++j){
                int a = j*32 + lane;
                bool sel = false;
                #pragma unroll
                for (int q2=0;q2<4;++q2) if (q2<k && idxs[q2]==a) sel = true;
                float v = sel ? 0.0f : fabsf(h[j]);
                if (v > b1v || (v == b1v && a < b1i)){ b2v = b1v; b1v = v; b1i = a; }
                else if (v > b2v) b2v = v;
            }
            #pragma unroll
            for (int off=16; off>0; off>>=1){
                float ov1 = __shfl_down_sync(0xffffffffu, b1v, off);
                int   oi1 = __shfl_down_sync(0xffffffffu, b1i, off);
                float ov2 = __shfl_down_sync(0xffffffffu, b2v, off);
                if (ov1 > b1v || (ov1 == b1v && oi1 < b1i)){
                    b2v = fmaxf(b1v, ov2); b1v = ov1; b1i = oi1;
                } else {
                    b2v = fmaxf(b2v, ov1);
                }
            }
            float bestv = __shfl_sync(0xffffffffu, b1v, 0);
            float runv  = __shfl_sync(0xffffffffu, b2v, 0);
            int bi      = __shfl_sync(0xffffffffu, b1i, 0);
            idxs[k] = bi;
            if (bestv - runv < TAU_ARG) flagged = 1;

            #pragma unroll
            for (int j=0;j<8;++j) gcol[k][j] = g_G[bi*256 + j*32 + lane];

            if (k == 0){
                L[0][0] = 1.0f;
            } else {
                float wv[4];
                #pragma unroll
                for (int r=0;r<4;++r){
                    if (r < k){
                        float v = g_G[idxs[r]*256 + bi];
                        #pragma unroll
                        for (int c2=0;c2<4;++c2) if (c2<r) v = __fmaf_rn(-L[r][c2], wv[c2], v);
                        wv[r] = __fdiv_rn(v, L[r][r]);
                    }
                }
                float ss = 0.f;
                #pragma unroll
                for (int c2=0;c2<4;++c2) if (c2<k) ss = __fadd_rn(ss, __fmul_rn(wv[c2], wv[c2]));
                #pragma unroll
                for (int c2=0;c2<4;++c2) if (c2<k) L[k][c2] = wv[c2];
                float rem = __fsub_rn(1.0f, ss);
                if (rem < TAU_CHOL) flagged = 1;
                L[k][k] = __fsqrt_rn(fmaxf(rem, 1e-12f));
            }
            // hbI = hb at atom bi (predicated select + shfl, no dyn reg index)
            {
                int jsel = bi >> 5;
                float v = hb[0];
                #pragma unroll
                for (int j=1;j<8;++j) if (jsel == j) v = hb[j];
                hbI[k] = __shfl_sync(0xffffffffu, v, bi & 31);
            }

            float y[4];
            #pragma unroll
            for (int r=0;r<4;++r) if (r<=k){
                float v = hbI[r];
                #pragma unroll
                for (int c2=0;c2<4;++c2) if (c2<r) v = __fmaf_rn(-L[r][c2], y[c2], v);
                y[r] = __fdiv_rn(v, L[r][r]);
            }
            #pragma unroll
            for (int r=3;r>=0;--r) if (r<=k){
                float v = y[r];
                #pragma unroll
                for (int c2=0;c2<4;++c2) if (c2>r && c2<=k) v = __fmaf_rn(-L[c2][r], xs[c2], v);
                xs[r] = __fdiv_rn(v, L[r][r]);
            }

            if (k < 3){
                #pragma unroll
                for (int j=0;j<8;++j){
                    float beta = 0.f;
                    #pragma unroll
                    for (int q2=0;q2<4;++q2)
                        if (q2<=k) beta = __fmaf_rn(xs[q2], gcol[q2][j], beta);
                    h[j] = __fsub_rn(hb[j], beta);
                }
            }
        }

        // quantize + reconstruct (DnT from global; L1/L2-resident)
        float q[4];
        #pragma unroll
        for (int k=0;k<4;++k) q[k] = mu_law_q_flag(xs[k], flagged);
        float r0 = 0.f, r1 = 0.f;
        #pragma unroll
        for (int k=0;k<4;++k){
            r0 = __fmaf_rn(q[k], g_DnT[idxs[k]*64 + lane],      r0);
            r1 = __fmaf_rn(q[k], g_DnT[idxs[k]*64 + lane + 32], r1);
        }
        R_s[lane*65 + sig]      = r0;
        R_s[(lane+32)*65 + sig] = r1;

        if (lane == 0){
            int gsig = blk*64 + sig;
            flag_s[sig] = flagged;
            g_fixloss[gsig] = 0.0f;
            if (flagged){
                int pos = atomicAdd(&g_qcount, 1);
                g_queue[pos] = gsig;
            }
        }
    }
    __syncthreads();

    // z_q write + loss (flagged signals excluded; fixed by k_fix)
    float lsum = 0.f;
    const int p  = t & 63;
    const int fl = flag_s[p];
    #pragma unroll
    for (int k = 0; k < 8; ++k){
        int idx = t + k*512;
        int c = idx >> 6;
        float x = X_s[idx];
        float r = R_s[c*65 + p];
        float d = __fsub_rn(r, x);
        if (fl){ dst[c*4096 + p] = x; }
        else   { dst[c*4096 + p] = __fadd_rn(x, d); lsum = __fmaf_rn(d, d, lsum); }
    }
    #pragma unroll
    for (int off=16; off>0; off>>=1) lsum += __shfl_down_sync(0xffffffffu, lsum, off);
    if (lane == 0) red[w] = lsum;
    __syncthreads();
    if (t == 0){
        float s = 0.f;
        #pragma unroll
        for (int w2=0; w2<16; ++w2) s += red[w2];
        g_partial[blk] = s;
    }
}

// ---------------- fp64 exact re-solve for flagged signals ----------------
__global__ void __launch_bounds__(256) k_fix(const float* __restrict__ z_e,
                                             float* __restrict__ out){
    __shared__ double xsh[8][64];
    const int lane = threadIdx.x & 31, wy = threadIdx.x >> 5;
    const int nwarps = gridDim.x * 8;
    const int w = blockIdx.x*8 + wy;
    const int cnt = g_qcount;
    const double INVD = 1.0 / log1p(50.0);

    for (int qi = w; qi < cnt; qi += nwarps){
        int gsig = g_queue[qi];
        int b = gsig >> 12, sp = gsig & 4095;
        const float* xp = z_e + (size_t)b*262144 + sp;
        float x0 = xp[(size_t)lane*4096], x1 = xp[(size_t)(lane+32)*4096];
        xsh[wy][lane] = (double)x0; xsh[wy][lane+32] = (double)x1;
        __syncwarp();

        double hb64[8], h64[8];
        #pragma unroll
        for (int j=0;j<8;++j){
            int a = j*32 + lane;
            double s0 = 0.0, s1 = 0.0;
            #pragma unroll
            for (int c = 0; c < 32; ++c){
                s0 = fma(g_Dn64[(2*c  )*NUM_A + a], xsh[wy][2*c  ], s0);
                s1 = fma(g_Dn64[(2*c+1)*NUM_A + a], xsh[wy][2*c+1], s1);
            }
            hb64[j] = s0 + s1; h64[j] = hb64[j];
        }

        int idxs[4]; double L[4][4], xs[4], hbI[4];
        #pragma unroll
        for (int k = 0; k < 4; ++k){
            double best = -1.0; int bi = 0;
            #pragma unroll
            for (int j=0;j<8;++j){
                int a = j*32 + lane;
                bool sel = false;
                #pragma unroll
                for (int q2=0;q2<4;++q2) if (q2<k && idxs[q2]==a) sel = true;
                double v = sel ? 0.0 : fabs(h64[j]);
                if (v > best || (v == best && a < bi)){ best = v; bi = a; }
            }
            #pragma unroll
            for (int off=16; off>0; off>>=1){
                double ov = __shfl_down_sync(0xffffffffu, best, off);
                int    oi = __shfl_down_sync(0xffffffffu, bi,   off);
                if (ov > best || (ov == best && oi < bi)){ best = ov; bi = oi; }
            }
            bi = __shfl_sync(0xffffffffu, bi, 0);
            idxs[k] = bi;

            if (k == 0){
                L[0][0] = 1.0;
            } else {
                double wv[4];
                #pragma unroll
                for (int r=0;r<4;++r){
                    if (r < k){
                        double v = g_G64[idxs[r]*NUM_A + bi];
                        #pragma unroll
                        for (int c2=0;c2<4;++c2) if (c2<r) v = fma(-L[r][c2], wv[c2], v);
                        wv[r] = v / L[r][r];
                    }
                }
                double ss = 0.0;
                #pragma unroll
                for (int c2=0;c2<4;++c2) if (c2<k) ss = fma(wv[c2], wv[c2], ss);
                #pragma unroll
                for (int c2=0;c2<4;++c2) if (c2<k) L[k][c2] = wv[c2];
                L[k][k] = sqrt(fmax(1.0 - ss, 1e-12));
            }
            {
                int jsel = bi >> 5;
                double v = hb64[0];
                #pragma unroll
                for (int j=1;j<8;++j) if (jsel == j) v = hb64[j];
                hbI[k] = __shfl_sync(0xffffffffu, v, bi & 31);
            }

            double y[4];
            #pragma unroll
            for (int r=0;r<4;++r) if (r<=k){
                double v = hbI[r];
                #pragma unroll
                for (int c2=0;c2<4;++c2) if (c2<r) v = fma(-L[r][c2], y[c2], v);
                y[r] = v / L[r][r];
            }
            #pragma unroll
            for (int r=3;r>=0;--r) if (r<=k){
                double v = y[r];
                #pragma unroll
                for (int c2=0;c2<4;++c2) if (c2>r && c2<=k) v = fma(-L[c2][r], xs[c2], v);
                xs[r] = v / L[r][r];
            }

            if (k < 3){
                #pragma unroll
                for (int j=0;j<8;++j){
                    int a = j*32 + lane;
                    double beta = 0.0;
                    #pragma unroll
                    for (int q2=0;q2<4;++q2)
                        if (q2<=k) beta = fma(xs[q2], g_G64[idxs[q2]*NUM_A + a], beta);
                    h64[j] = hb64[j] - beta;
                }
            }
        }

        float r0 = 0.f, r1 = 0.f;
        #pragma unroll
        for (int k=0;k<4;++k){
            double v = xs[k];
            double cl = fmin(fmax(v, -3.0), 3.0);
            double c  = cl / 3.0;
            double enc = copysign(log1p(fabs(c)*50.0) * INVD, c);
            double scaled = (enc + 1.0) * 7.5;
            int bq = (int)rint(scaled);
            bq = max(0, min(15, bq));
            double z = (double)bq * (2.0/15.0) - 1.0;
            float qk = (float)copysign(expm1(fabs(z)/INVD)/50.0*3.0, z);
            r0 = __fmaf_rn(qk, g_DnT[idxs[k]*64 + lane],      r0);
            r1 = __fmaf_rn(qk, g_DnT[idxs[k]*64 + lane + 32], r1);
        }
        float d0 = __fsub_rn(r0, x0), d1 = __fsub_rn(r1, x1);
        out[(size_t)b*262144 + (size_t)lane*4096 + sp]      = __fadd_rn(x0, d0);
        out[(size_t)b*262144 + (size_t)(lane+32)*4096 + sp] = __fadd_rn(x1, d1);
        float ls = __fmaf_rn(d0, d0, __fmul_rn(d1, d1));
        #pragma unroll
        for (int off=16; off>0; off>>=1) ls += __shfl_down_sync(0xffffffffu, ls, off);
        if (lane == 0) g_fixloss[gsig] = ls;
        __syncwarp();
    }
}

// ---------------- deterministic parallel fixloss reduction ----------------
__global__ void k_fixred(){
    __shared__ float red[256];
    int base = blockIdx.x * 256;
    red[threadIdx.x] = g_fixloss[base + threadIdx.x];
    __syncthreads();
    for (int o = 128; o > 0; o >>= 1){
        if (threadIdx.x < o) red[threadIdx.x] += red[threadIdx.x + o];
        __syncthreads();
    }
    if (threadIdx.x == 0) g_partial2[blockIdx.x] = red[0];
}

// ---------------- finalize ----------------
__global__ void k_final(float* __restrict__ out, int out_size){
    __shared__ float red[256];
    float s = 0.f;
    for (int i = threadIdx.x; i < NBLOCKS; i += 256) s += g_partial[i];
    for (int i = threadIdx.x; i < 512; i += 256) s += g_partial2[i];
    red[threadIdx.x] = s;
    __syncthreads();
    for (int o = 128; o > 0; o >>= 1){
        if (threadIdx.x < o) red[threadIdx.x] += red[threadIdx.x + o];
        __syncthreads();
    }
    if (threadIdx.x == 0 && out_size > NELEM)
        out[NELEM] = 1.25f * red[0] / (float)NELEM;
}

// ---------------- launch ----------------
extern "C" void kernel_launch(void* const* d_in, const int* in_sizes, int n_in,
                              void* d_out, int out_size){
    const float* z_e  = (const float*)d_in[0];
    const float* dict = (const float*)d_in[1];
    float* out = (float*)d_out;

    cudaFuncSetAttribute(k_main, cudaFuncAttributeMaxDynamicSharedMemorySize, SM_BYTES);

    k_normalize<<<1, 256>>>(dict);
    k_gram<<<256, 256>>>();
    k_main<<<NBLOCKS, 512, SM_BYTES>>>(z_e, out);
    k_fix<<<296, 256>>>(z_e, out);
    k_fixred<<<512, 256>>>();
    k_final<<<1, 256>>>(out, out_size);
}

// round 11
// speedup vs baseline: 2.9760x; 1.1486x over previous
#include <cuda_runtime.h>
#include <math.h>

#define NUM_A 256
#define DIM 64
#define NSIG_TOTAL (32*64*64)
#define NBLOCKS (NSIG_TOTAL/64)      // 2048
#define NELEM 8388608

#define INV_LOG1P_MU 0.25433462858092786f
#define TAU_ARG  1e-4f
#define TAU_BIN  6e-4f
#define TAU_CHOL 1e-2f

// device-global scratch (no allocation allowed)
__device__ float  g_Dn[DIM*NUM_A];     // [c][a]
__device__ float  g_DnT[NUM_A*DIM];    // [a][c]
__device__ float  g_G[NUM_A*NUM_A];
__device__ double g_Dn64[DIM*NUM_A];
__device__ double g_G64[NUM_A*NUM_A];
__device__ float  g_partial[NBLOCKS];
__device__ float  g_partial2[512];
__device__ float  g_fixloss[NSIG_TOTAL];
__device__ int    g_qcount;
__device__ int    g_queue[NSIG_TOTAL];

// ---------------- f32x2 helpers ----------------
#define FMA2(d, a, b, c) asm("fma.rn.f32x2 %0, %1, %2, %3;" : "=l"(d) : "l"(a), "l"(b), "l"(c))
#define PACKDUP(out, f)  asm("mov.b64 %0, {%1, %1};" : "=l"(out) : "r"(__float_as_uint(f)))
#define UNPACK2(lo, hi, in) asm("mov.b64 {%0, %1}, %2;" : "=r"(lo), "=r"(hi) : "l"(in))

// ---------------- prep (16-way parallel over c-chunks) ----------------
__global__ void k_normalize(const float* __restrict__ dict){
    int a = threadIdx.x;
    if (blockIdx.x == 0 && a == 0) g_qcount = 0;
    float s = 0.f;  double s64 = 0.0;
    #pragma unroll
    for (int c = 0; c < DIM; ++c){
        float v = dict[c*NUM_A + a];
        s   = __fadd_rn(s, __fmul_rn(v, v));
        s64 = fma((double)v, (double)v, s64);
    }
    float  den   = fmaxf(__fsqrt_rn(s), 1e-10f);
    double den64 = fmax(sqrt(s64), 1e-10);
    int c0 = blockIdx.x * 4;
    #pragma unroll
    for (int cc = 0; cc < 4; ++cc){
        int c = c0 + cc;
        float v = __fdiv_rn(dict[c*NUM_A + a], den);
        g_Dn[c*NUM_A + a]  = v;
        g_DnT[a*DIM + c]   = v;
        g_Dn64[c*NUM_A + a] = (double)dict[c*NUM_A + a] / den64;
    }
}

__global__ void k_gram(){
    __shared__ float  di[DIM];
    __shared__ double di64[DIM];
    int i = blockIdx.x, j = threadIdx.x;
    if (j < DIM){ di[j] = g_DnT[i*DIM + j]; di64[j] = g_Dn64[j*NUM_A + i]; }
    __syncthreads();
    float s = 0.f;  double s64 = 0.0;
    #pragma unroll
    for (int c = 0; c < DIM; ++c){
        s   = __fmaf_rn(di[c], g_Dn[c*NUM_A + j], s);
        s64 = fma(di64[c], g_Dn64[c*NUM_A + j], s64);
    }
    g_G[i*NUM_A + j]   = s;
    g_G64[i*NUM_A + j] = s64;
}

// ---------------- mu-law (fp32, with boundary flag) ----------------
__device__ __forceinline__ float mu_law_q_flag(float v, int &flag){
    float cl = fminf(fmaxf(v, -3.0f), 3.0f);
    float c  = __fdiv_rn(cl, 3.0f);
    float enc = copysignf(__fmul_rn(log1pf(__fmul_rn(fabsf(c), 50.0f)), INV_LOG1P_MU), c);
    float scaled = __fmul_rn(__fadd_rn(enc, 1.0f), 7.5f);
    float fb = rintf(scaled);
    if (0.5f - fabsf(scaled - fb) < TAU_BIN) flag = 1;
    int b = (int)fb;
    b = max(0, min(15, b));
    float z = __fsub_rn(__fmul_rn((float)b, 2.0f/15.0f), 1.0f);
    float e = expm1f(__fdiv_rn(fabsf(z), INV_LOG1P_MU));
    return copysignf(__fmul_rn(__fdiv_rn(e, 50.0f), 3.0f), z);
}

// ---------------- main fused kernel: 512 thr, atom layout a = lane*8 + j ----
// smem floats: Dn_s [64][256] swizzled @0 (16384), X_s [64][64] @16384 (4096),
//              R_s [64][65] @20480 (4160).  Total 24640 floats = 98560 B.
#define SM_DN 0
#define SM_X  16384
#define SM_R  20480
#define SM_FLOATS 24640
#define SM_BYTES (SM_FLOATS*4)

__global__ void __launch_bounds__(512,1) k_main(const float* __restrict__ z_e,
                                               float* __restrict__ out){
    extern __shared__ float S[];
    float* Dn_s = S + SM_DN;
    float* X_s  = S + SM_X;
    float* R_s  = S + SM_R;
    __shared__ int flag_s[64];
    __shared__ float red[16];

    const int t    = threadIdx.x;
    const int w    = t >> 5;          // warp 0..15 -> signals w*4..w*4+3
    const int lane = t & 31;
    const int blk  = blockIdx.x;
    const int b    = blk >> 6;
    const int p0   = (blk & 63) << 6;
    const float* src = z_e + (size_t)b*262144 + p0;
    float*       dst = out + (size_t)b*262144 + p0;

    // --- load Dn tile with XOR-unit swizzle: element (c,a) ->
    //     float offset c*256 + (u ^ ((u>>3)&7))*4 + (a&3), u = a>>2 ---
    {
        #pragma unroll
        for (int k = 0; k < 32; ++k){
            int idx = t + k*512;
            int c = idx >> 8, a = idx & 255;
            int u = a >> 2;
            int pu = u ^ ((u >> 3) & 7);
            Dn_s[c*256 + pu*4 + (a & 3)] = g_Dn[idx];
        }
    }
    // --- load X tile: X_s[c][p] ---
    {
        float4* xd = (float4*)X_s;
        #pragma unroll
        for (int k = 0; k < 2; ++k){
            int idx4 = t + k*512;
            int c = idx4 >> 4, p4 = idx4 & 15;
            xd[idx4] = *(const float4*)(src + c*4096 + p4*4);
        }
    }
    __syncthreads();

    // --- GEMM into packed registers: acc2[si][jp] packs H[w*4+si][lane*8+2jp(+1)]
    //     ascending-c, single accumulator per element, per-half IEEE FMA ->
    //     bit-identical H to previous rounds ---
    const int u0 = 2*lane,     pu0 = u0 ^ ((u0 >> 3) & 7);
    const int u1 = 2*lane + 1, pu1 = u1 ^ ((u1 >> 3) & 7);
    unsigned long long acc2[4][4];
    #pragma unroll
    for (int si=0; si<4; ++si)
        #pragma unroll
        for (int jp=0; jp<4; ++jp) acc2[si][jp] = 0ULL;
    #pragma unroll 2
    for (int c = 0; c < 64; ++c){
        ulonglong2 d0 = *(const ulonglong2*)&Dn_s[c*256 + pu0*4];   // j=0,1 | 2,3
        ulonglong2 d1 = *(const ulonglong2*)&Dn_s[c*256 + pu1*4];   // j=4,5 | 6,7
        float4 xq = *(const float4*)&X_s[c*64 + w*4];
        unsigned long long xd0, xd1, xd2, xd3;
        PACKDUP(xd0, xq.x); PACKDUP(xd1, xq.y); PACKDUP(xd2, xq.z); PACKDUP(xd3, xq.w);
        FMA2(acc2[0][0], xd0, d0.x, acc2[0][0]);
        FMA2(acc2[0][1], xd0, d0.y, acc2[0][1]);
        FMA2(acc2[0][2], xd0, d1.x, acc2[0][2]);
        FMA2(acc2[0][3], xd0, d1.y, acc2[0][3]);
        FMA2(acc2[1][0], xd1, d0.x, acc2[1][0]);
        FMA2(acc2[1][1], xd1, d0.y, acc2[1][1]);
        FMA2(acc2[1][2], xd1, d1.x, acc2[1][2]);
        FMA2(acc2[1][3], xd1, d1.y, acc2[1][3]);
        FMA2(acc2[2][0], xd2, d0.x, acc2[2][0]);
        FMA2(acc2[2][1], xd2, d0.y, acc2[2][1]);
        FMA2(acc2[2][2], xd2, d1.x, acc2[2][2]);
        FMA2(acc2[2][3], xd2, d1.y, acc2[2][3]);
        FMA2(acc2[3][0], xd3, d0.x, acc2[3][0]);
        FMA2(acc2[3][1], xd3, d0.y, acc2[3][1]);
        FMA2(acc2[3][2], xd3, d1.x, acc2[3][2]);
        FMA2(acc2[3][3], xd3, d1.y, acc2[3][3]);
    }

    // --- OMP per signal (4 per warp); atom a = lane*8 + j ---
    for (int i = 0; i < 4; ++i){
        const int sig = w*4 + i;
        float hb[8], h[8];
        #pragma unroll
        for (int jp=0; jp<4; ++jp){
            unsigned int lo, hi;
            UNPACK2(lo, hi, acc2[i][jp]);
            hb[2*jp]   = __uint_as_float(lo);
            hb[2*jp+1] = __uint_as_float(hi);
            h[2*jp] = hb[2*jp]; h[2*jp+1] = hb[2*jp+1];
        }

        int   idxs[4];
        float L[4][4];
        float hbI[4];
        float xs[4];
        float gcol[4][8];
        int   flagged = 0;
        unsigned int msk = 0;            // bit j set = atom lane*8+j selected

        #pragma unroll
        for (int k = 0; k < 4; ++k){
            // single-pass top-2 masked argmax of |h| (ascending-a scan:
            // strict > keeps lowest index within thread)
            float b1v = -1.0f, b2v = -1.0f; int b1i = 0;
            #pragma unroll
            for (int j=0;j<8;++j){
                float v = ((msk >> j) & 1u) ? 0.0f : fabsf(h[j]);
                if (v > b1v){ b2v = b1v; b1v = v; b1i = lane*8 + j; }
                else if (v > b2v) b2v = v;
            }
            #pragma unroll
            for (int off=16; off>0; off>>=1){
                float ov1 = __shfl_down_sync(0xffffffffu, b1v, off);
                int   oi1 = __shfl_down_sync(0xffffffffu, b1i, off);
                float ov2 = __shfl_down_sync(0xffffffffu, b2v, off);
                if (ov1 > b1v || (ov1 == b1v && oi1 < b1i)){
                    b2v = fmaxf(b1v, ov2); b1v = ov1; b1i = oi1;
                } else {
                    b2v = fmaxf(b2v, ov1);
                }
            }
            float bestv = __shfl_sync(0xffffffffu, b1v, 0);
            float runv  = __shfl_sync(0xffffffffu, b2v, 0);
            int bi      = __shfl_sync(0xffffffffu, b1i, 0);
            idxs[k] = bi;
            if (bestv - runv < TAU_ARG) flagged = 1;
            if (lane == (bi >> 3)) msk |= 1u << (bi & 7);

            // G column: 8 contiguous floats per lane -> 2x LDG.128, coalesced
            {
                float4 ga = *(const float4*)&g_G[bi*256 + lane*8];
                float4 gb = *(const float4*)&g_G[bi*256 + lane*8 + 4];
                gcol[k][0]=ga.x; gcol[k][1]=ga.y; gcol[k][2]=ga.z; gcol[k][3]=ga.w;
                gcol[k][4]=gb.x; gcol[k][5]=gb.y; gcol[k][6]=gb.z; gcol[k][7]=gb.w;
            }

            if (k == 0){
                L[0][0] = 1.0f;
            } else {
                float wv[4];
                #pragma unroll
                for (int r=0;r<4;++r){
                    if (r < k){
                        float v = g_G[idxs[r]*256 + bi];
                        #pragma unroll
                        for (int c2=0;c2<4;++c2) if (c2<r) v = __fmaf_rn(-L[r][c2], wv[c2], v);
                        wv[r] = __fdiv_rn(v, L[r][r]);
                    }
                }
                float ss = 0.f;
                #pragma unroll
                for (int c2=0;c2<4;++c2) if (c2<k) ss = __fadd_rn(ss, __fmul_rn(wv[c2], wv[c2]));
                #pragma unroll
                for (int c2=0;c2<4;++c2) if (c2<k) L[k][c2] = wv[c2];
                float rem = __fsub_rn(1.0f, ss);
                if (rem < TAU_CHOL) flagged = 1;
                L[k][k] = __fsqrt_rn(fmaxf(rem, 1e-12f));
            }
            // hbI = hb at atom bi (predicated select + shfl from owner lane)
            {
                int jsel = bi & 7;
                float v = hb[0];
                #pragma unroll
                for (int j=1;j<8;++j) if (jsel == j) v = hb[j];
                hbI[k] = __shfl_sync(0xffffffffu, v, bi >> 3);
            }

            float y[4];
            #pragma unroll
            for (int r=0;r<4;++r) if (r<=k){
                float v = hbI[r];
                #pragma unroll
                for (int c2=0;c2<4;++c2) if (c2<r) v = __fmaf_rn(-L[r][c2], y[c2], v);
                y[r] = __fdiv_rn(v, L[r][r]);
            }
            #pragma unroll
            for (int r=3;r>=0;--r) if (r<=k){
                float v = y[r];
                #pragma unroll
                for (int c2=0;c2<4;++c2) if (c2>r && c2<=k) v = __fmaf_rn(-L[c2][r], xs[c2], v);
                xs[r] = __fdiv_rn(v, L[r][r]);
            }

            if (k < 3){
                #pragma unroll
                for (int j=0;j<8;++j){
                    float beta = 0.f;
                    #pragma unroll
                    for (int q2=0;q2<4;++q2)
                        if (q2<=k) beta = __fmaf_rn(xs[q2], gcol[q2][j], beta);
                    h[j] = __fsub_rn(hb[j], beta);
                }
            }
        }

        // quantize + reconstruct (DnT from global; L1/L2-resident)
        float q[4];
        #pragma unroll
        for (int k=0;k<4;++k) q[k] = mu_law_q_flag(xs[k], flagged);
        float r0 = 0.f, r1 = 0.f;
        #pragma unroll
        for (int k=0;k<4;++k){
            r0 = __fmaf_rn(q[k], g_DnT[idxs[k]*64 + lane],      r0);
            r1 = __fmaf_rn(q[k], g_DnT[idxs[k]*64 + lane + 32], r1);
        }
        R_s[lane*65 + sig]      = r0;
        R_s[(lane+32)*65 + sig] = r1;

        if (lane == 0){
            int gsig = blk*64 + sig;
            flag_s[sig] = flagged;
            g_fixloss[gsig] = 0.0f;
            if (flagged){
                int pos = atomicAdd(&g_qcount, 1);
                g_queue[pos] = gsig;
            }
        }
    }
    __syncthreads();

    // z_q write + loss (flagged signals excluded; fixed by k_fix)
    float lsum = 0.f;
    const int p  = t & 63;
    const int fl = flag_s[p];
    #pragma unroll
    for (int k = 0; k < 8; ++k){
        int idx = t + k*512;
        int c = idx >> 6;
        float x = X_s[idx];
        float r = R_s[c*65 + p];
        float d = __fsub_rn(r, x);
        if (fl){ dst[c*4096 + p] = x; }
        else   { dst[c*4096 + p] = __fadd_rn(x, d); lsum = __fmaf_rn(d, d, lsum); }
    }
    #pragma unroll
    for (int off=16; off>0; off>>=1) lsum += __shfl_down_sync(0xffffffffu, lsum, off);
    if (lane == 0) red[w] = lsum;
    __syncthreads();
    if (t == 0){
        float s = 0.f;
        #pragma unroll
        for (int w2=0; w2<16; ++w2) s += red[w2];
        g_partial[blk] = s;
    }
}

// ---------------- fp64 exact re-solve for flagged signals ----------------
__global__ void __launch_bounds__(256) k_fix(const float* __restrict__ z_e,
                                             float* __restrict__ out){
    __shared__ double xsh[8][64];
    const int lane = threadIdx.x & 31, wy = threadIdx.x >> 5;
    const int nwarps = gridDim.x * 8;
    const int w = blockIdx.x*8 + wy;
    const int cnt = g_qcount;
    const double INVD = 1.0 / log1p(50.0);

    for (int qi = w; qi < cnt; qi += nwarps){
        int gsig = g_queue[qi];
        int b = gsig >> 12, sp = gsig & 4095;
        const float* xp = z_e + (size_t)b*262144 + sp;
        float x0 = xp[(size_t)lane*4096], x1 = xp[(size_t)(lane+32)*4096];
        xsh[wy][lane] = (double)x0; xsh[wy][lane+32] = (double)x1;
        __syncwarp();

        double hb64[8], h64[8];
        #pragma unroll
        for (int j=0;j<8;++j){
            int a = j*32 + lane;
            double s0 = 0.0, s1 = 0.0;
            #pragma unroll
            for (int c = 0; c < 32; ++c){
                s0 = fma(g_Dn64[(2*c  )*NUM_A + a], xsh[wy][2*c  ], s0);
                s1 = fma(g_Dn64[(2*c+1)*NUM_A + a], xsh[wy][2*c+1], s1);
            }
            hb64[j] = s0 + s1; h64[j] = hb64[j];
        }

        int idxs[4]; double L[4][4], xs[4], hbI[4];
        #pragma unroll
        for (int k = 0; k < 4; ++k){
            double best = -1.0; int bi = 0;
            #pragma unroll
            for (int j=0;j<8;++j){
                int a = j*32 + lane;
                bool sel = false;
                #pragma unroll
                for (int q2=0;q2<4;++q2) if (q2<k && idxs[q2]==a) sel = true;
                double v = sel ? 0.0 : fabs(h64[j]);
                if (v > best || (v == best && a < bi)){ best = v; bi = a; }
            }
            #pragma unroll
            for (int off=16; off>0; off>>=1){
                double ov = __shfl_down_sync(0xffffffffu, best, off);
                int    oi = __shfl_down_sync(0xffffffffu, bi,   off);
                if (ov > best || (ov == best && oi < bi)){ best = ov; bi = oi; }
            }
            bi = __shfl_sync(0xffffffffu, bi, 0);
            idxs[k] = bi;

            if (k == 0){
                L[0][0] = 1.0;
            } else {
                double wv[4];
                #pragma unroll
                for (int r=0;r<4;++r){
                    if (r < k){
                        double v = g_G64[idxs[r]*NUM_A + bi];
                        #pragma unroll
                        for (int c2=0;c2<4;++c2) if (c2<r) v = fma(-L[r][c2], wv[c2], v);
                        wv[r] = v / L[r][r];
                    }
                }
                double ss = 0.0;
                #pragma unroll
                for (int c2=0;c2<4;++c2) if (c2<k) ss = fma(wv[c2], wv[c2], ss);
                #pragma unroll
                for (int c2=0;c2<4;++c2) if (c2<k) L[k][c2] = wv[c2];
                L[k][k] = sqrt(fmax(1.0 - ss, 1e-12));
            }
            {
                int jsel = bi >> 5;
                double v = hb64[0];
                #pragma unroll
                for (int j=1;j<8;++j) if (jsel == j) v = hb64[j];
                hbI[k] = __shfl_sync(0xffffffffu, v, bi & 31);
            }

            double y[4];
            #pragma unroll
            for (int r=0;r<4;++r) if (r<=k){
                double v = hbI[r];
                #pragma unroll
                for (int c2=0;c2<4;++c2) if (c2<r) v = fma(-L[r][c2], y[c2], v);
                y[r] = v / L[r][r];
            }
            #pragma unroll
            for (int r=3;r>=0;--r) if (r<=k){
                double v = y[r];
                #pragma unroll
                for (int c2=0;c2<4;++c2) if (c2>r && c2<=k) v = fma(-L[c2][r], xs[c2], v);
                xs[r] = v / L[r][r];
            }

            if (k < 3){
                #pragma unroll
                for (int j=0;j<8;++j){
                    int a = j*32 + lane;
                    double beta = 0.0;
                    #pragma unroll
                    for (int q2=0;q2<4;++q2)
                        if (q2<=k) beta = fma(xs[q2], g_G64[idxs[q2]*NUM_A + a], beta);
                    h64[j] = hb64[j] - beta;
                }
            }
        }

        float r0 = 0.f, r1 = 0.f;
        #pragma unroll
        for (int k=0;k<4;++k){
            double v = xs[k];
            double cl = fmin(fmax(v, -3.0), 3.0);
            double c  = cl / 3.0;
            double enc = copysign(log1p(fabs(c)*50.0) * INVD, c);
            double scaled = (enc + 1.0) * 7.5;
            int bq = (int)rint(scaled);
            bq = max(0, min(15, bq));
            double z = (double)bq * (2.0/15.0) - 1.0;
            float qk = (float)copysign(expm1(fabs(z)/INVD)/50.0*3.0, z);
            r0 = __fmaf_rn(qk, g_DnT[idxs[k]*64 + lane],      r0);
            r1 = __fmaf_rn(qk, g_DnT[idxs[k]*64 + lane + 32], r1);
        }
        float d0 = __fsub_rn(r0, x0), d1 = __fsub_rn(r1, x1);
        out[(size_t)b*262144 + (size_t)lane*4096 + sp]      = __fadd_rn(x0, d0);
        out[(size_t)b*262144 + (size_t)(lane+32)*4096 + sp] = __fadd_rn(x1, d1);
        float ls = __fmaf_rn(d0, d0, __fmul_rn(d1, d1));
        #pragma unroll
        for (int off=16; off>0; off>>=1) ls += __shfl_down_sync(0xffffffffu, ls, off);
        if (lane == 0) g_fixloss[gsig] = ls;
        __syncwarp();
    }
}

// ---------------- deterministic parallel fixloss reduction ----------------
__global__ void k_fixred(){
    __shared__ float red[256];
    int base = blockIdx.x * 256;
    red[threadIdx.x] = g_fixloss[base + threadIdx.x];
    __syncthreads();
    for (int o = 128; o > 0; o >>= 1){
        if (threadIdx.x < o) red[threadIdx.x] += red[threadIdx.x + o];
        __syncthreads();
    }
    if (threadIdx.x == 0) g_partial2[blockIdx.x] = red[0];
}

// ---------------- finalize ----------------
__global__ void k_final(float* __restrict__ out, int out_size){
    __shared__ float red[256];
    float s = 0.f;
    for (int i = threadIdx.x; i < NBLOCKS; i += 256) s += g_partial[i];
    for (int i = threadIdx.x; i < 512; i += 256) s += g_partial2[i];
    red[threadIdx.x] = s;
    __syncthreads();
    for (int o = 128; o > 0; o >>= 1){
        if (threadIdx.x < o) red[threadIdx.x] += red[threadIdx.x + o];
        __syncthreads();
    }
    if (threadIdx.x == 0 && out_size > NELEM)
        out[NELEM] = 1.25f * red[0] / (float)NELEM;
}

// ---------------- launch ----------------
extern "C" void kernel_launch(void* const* d_in, const int* in_sizes, int n_in,
                              void* d_out, int out_size){
    const float* z_e  = (const float*)d_in[0];
    const float* dict = (const float*)d_in[1];
    float* out = (float*)d_out;

    cudaFuncSetAttribute(k_main, cudaFuncAttributeMaxDynamicSharedMemorySize, SM_BYTES);

    k_normalize<<<16, 256>>>(dict);
    k_gram<<<256, 256>>>();
    k_main<<<NBLOCKS, 512, SM_BYTES>>>(z_e, out);
    k_fix<<<296, 256>>>(z_e, out);
    k_fixred<<<512, 256>>>();
    k_final<<<1, 256>>>(out, out_size);
}

// round 13
// speedup vs baseline: 3.4201x; 1.1492x over previous
#include <cuda_runtime.h>
#include <math.h>

#define NUM_A 256
#define DIM 64
#define NSIG_TOTAL (32*64*64)
#define NBLOCKS (NSIG_TOTAL/64)      // 2048
#define NELEM 8388608

#define INV_LOG1P_MU 0.25433462858092786f
#define TAU_ARG  1e-4f
#define TAU_BIN  6e-4f
#define TAU_CHOL 1e-2f

// device-global scratch (no allocation allowed)
__device__ float  g_Dn[DIM*NUM_A];     // [c][a]
__device__ float  g_DnT[NUM_A*DIM];    // [a][c]
__device__ float  g_G[NUM_A*NUM_A];
__device__ double g_Dn64[DIM*NUM_A];
__device__ double g_G64[NUM_A*NUM_A];
__device__ float  g_dec[16];           // mu-law decode LUT
__device__ float  g_partial[NBLOCKS];
__device__ float  g_partial2[512];
__device__ float  g_fixloss[NSIG_TOTAL];
__device__ int    g_qcount;
__device__ int    g_queue[NSIG_TOTAL];

// ---------------- f32x2 helpers ----------------
#define FMA2(d, a, b, c) asm("fma.rn.f32x2 %0, %1, %2, %3;" : "=l"(d) : "l"(a), "l"(b), "l"(c))
#define PACKDUP(out, f)  asm("mov.b64 %0, {%1, %1};" : "=l"(out) : "r"(__float_as_uint(f)))
#define UNPACK2(lo, hi, in) asm("mov.b64 {%0, %1}, %2;" : "=r"(lo), "=r"(hi) : "l"(in))

// ---------------- prep (16-way parallel over c-chunks) ----------------
__global__ void k_normalize(const float* __restrict__ dict){
    int a = threadIdx.x;
    if (blockIdx.x == 0 && a == 0){
        g_qcount = 0;
        const double INVD = 1.0 / log1p(50.0);
        #pragma unroll
        for (int b = 0; b < 16; ++b){
            double z = (double)b * (2.0/15.0) - 1.0;
            g_dec[b] = (float)copysign(expm1(fabs(z)/INVD)/50.0*3.0, z);
        }
    }
    float s = 0.f;  double s64 = 0.0;
    #pragma unroll
    for (int c = 0; c < DIM; ++c){
        float v = dict[c*NUM_A + a];
        s   = __fadd_rn(s, __fmul_rn(v, v));
        s64 = fma((double)v, (double)v, s64);
    }
    float  den   = fmaxf(__fsqrt_rn(s), 1e-10f);
    double den64 = fmax(sqrt(s64), 1e-10);
    int c0 = blockIdx.x * 4;
    #pragma unroll
    for (int cc = 0; cc < 4; ++cc){
        int c = c0 + cc;
        float v = __fdiv_rn(dict[c*NUM_A + a], den);
        g_Dn[c*NUM_A + a]  = v;
        g_DnT[a*DIM + c]   = v;
        g_Dn64[c*NUM_A + a] = (double)dict[c*NUM_A + a] / den64;
    }
}

__global__ void k_gram(){
    __shared__ float  di[DIM];
    __shared__ double di64[DIM];
    int i = blockIdx.x, j = threadIdx.x;
    if (j < DIM){ di[j] = g_DnT[i*DIM + j]; di64[j] = g_Dn64[j*NUM_A + i]; }
    __syncthreads();
    float s = 0.f;  double s64 = 0.0;
    #pragma unroll
    for (int c = 0; c < DIM; ++c){
        s   = __fmaf_rn(di[c], g_Dn[c*NUM_A + j], s);
        s64 = fma(di64[c], g_Dn64[c*NUM_A + j], s64);
    }
    g_G[i*NUM_A + j]   = s;
    g_G64[i*NUM_A + j] = s64;
}

// ---------------- mu-law (fast fp32 encode + LUT decode, boundary flag) -----
__device__ __forceinline__ float mu_law_q_flag(float v, int &flag){
    float cl = fminf(fmaxf(v, -3.0f), 3.0f);
    float c  = __fmul_rn(cl, 0.3333333432674408f);   // ~1ulp vs div; << TAU_BIN
    float enc = copysignf(__fmul_rn(log1pf(__fmul_rn(fabsf(c), 50.0f)), INV_LOG1P_MU), c);
    float scaled = __fmul_rn(__fadd_rn(enc, 1.0f), 7.5f);
    float fb = rintf(scaled);
    if (0.5f - fabsf(scaled - fb) < TAU_BIN) flag = 1;
    int b = (int)fb;
    b = max(0, min(15, b));
    return g_dec[b];                                  // warp-uniform broadcast
}

// ---------------- main fused kernel: 512 thr, atom layout a = lane*8 + j ----
// smem floats: Dn_s [64][256] swizzled @0 (16384), X_s [64][64] @16384 (4096),
//              R_s [64][65] @20480 (4160).  Total 24640 floats = 98560 B.
#define SM_DN 0
#define SM_X  16384
#define SM_R  20480
#define SM_FLOATS 24640
#define SM_BYTES (SM_FLOATS*4)

__global__ void __launch_bounds__(512,1) k_main(const float* __restrict__ z_e,
                                               float* __restrict__ out){
    extern __shared__ float S[];
    float* Dn_s = S + SM_DN;
    float* X_s  = S + SM_X;
    float* R_s  = S + SM_R;
    __shared__ int flag_s[64];
    __shared__ float red[16];

    const int t    = threadIdx.x;
    const int w    = t >> 5;          // warp 0..15 -> signals w*4..w*4+3
    const int lane = t & 31;
    const int blk  = blockIdx.x;
    const int b    = blk >> 6;
    const int p0   = (blk & 63) << 6;
    const float* src = z_e + (size_t)b*262144 + p0;
    float*       dst = out + (size_t)b*262144 + p0;

    // --- load Dn tile with XOR-unit swizzle ---
    {
        #pragma unroll
        for (int k = 0; k < 32; ++k){
            int idx = t + k*512;
            int c = idx >> 8, a = idx & 255;
            int u = a >> 2;
            int pu = u ^ ((u >> 3) & 7);
            Dn_s[c*256 + pu*4 + (a & 3)] = g_Dn[idx];
        }
    }
    // --- load X tile: X_s[c][p] ---
    {
        float4* xd = (float4*)X_s;
        #pragma unroll
        for (int k = 0; k < 2; ++k){
            int idx4 = t + k*512;
            int c = idx4 >> 4, p4 = idx4 & 15;
            xd[idx4] = *(const float4*)(src + c*4096 + p4*4);
        }
    }
    __syncthreads();

    // --- GEMM into packed registers (per-half IEEE FMA -> bit-identical H) ---
    const int u0 = 2*lane,     pu0 = u0 ^ ((u0 >> 3) & 7);
    const int u1 = 2*lane + 1, pu1 = u1 ^ ((u1 >> 3) & 7);
    unsigned long long acc2[4][4];
    #pragma unroll
    for (int si=0; si<4; ++si)
        #pragma unroll
        for (int jp=0; jp<4; ++jp) acc2[si][jp] = 0ULL;
    #pragma unroll 2
    for (int c = 0; c < 64; ++c){
        ulonglong2 d0 = *(const ulonglong2*)&Dn_s[c*256 + pu0*4];
        ulonglong2 d1 = *(const ulonglong2*)&Dn_s[c*256 + pu1*4];
        float4 xq = *(const float4*)&X_s[c*64 + w*4];
        unsigned long long xd0, xd1, xd2, xd3;
        PACKDUP(xd0, xq.x); PACKDUP(xd1, xq.y); PACKDUP(xd2, xq.z); PACKDUP(xd3, xq.w);
        FMA2(acc2[0][0], xd0, d0.x, acc2[0][0]);
        FMA2(acc2[0][1], xd0, d0.y, acc2[0][1]);
        FMA2(acc2[0][2], xd0, d1.x, acc2[0][2]);
        FMA2(acc2[0][3], xd0, d1.y, acc2[0][3]);
        FMA2(acc2[1][0], xd1, d0.x, acc2[1][0]);
        FMA2(acc2[1][1], xd1, d0.y, acc2[1][1]);
        FMA2(acc2[1][2], xd1, d1.x, acc2[1][2]);
        FMA2(acc2[1][3], xd1, d1.y, acc2[1][3]);
        FMA2(acc2[2][0], xd2, d0.x, acc2[2][0]);
        FMA2(acc2[2][1], xd2, d0.y, acc2[2][1]);
        FMA2(acc2[2][2], xd2, d1.x, acc2[2][2]);
        FMA2(acc2[2][3], xd2, d1.y, acc2[2][3]);
        FMA2(acc2[3][0], xd3, d0.x, acc2[3][0]);
        FMA2(acc2[3][1], xd3, d0.y, acc2[3][1]);
        FMA2(acc2[3][2], xd3, d1.x, acc2[3][2]);
        FMA2(acc2[3][3], xd3, d1.y, acc2[3][3]);
    }

    // --- OMP per signal (4 per warp); atom a = lane*8 + j ---
    for (int i = 0; i < 4; ++i){
        const int sig = w*4 + i;
        float hb[8], h[8];
        #pragma unroll
        for (int jp=0; jp<4; ++jp){
            unsigned int lo, hi;
            UNPACK2(lo, hi, acc2[i][jp]);
            hb[2*jp]   = __uint_as_float(lo);
            hb[2*jp+1] = __uint_as_float(hi);
            h[2*jp] = hb[2*jp]; h[2*jp+1] = hb[2*jp+1];
        }

        int   idxs[4];
        float L[4][4];
        float rinv[4];                 // reciprocal of L diagonal (MUFU-based)
        float hbI[4];
        float xs[4];
        float gcol[4][8];
        int   flagged = 0;
        unsigned int msk = 0;

        #pragma unroll
        for (int k = 0; k < 4; ++k){
            // single-pass top-2 masked argmax of |h|
            float b1v = -1.0f, b2v = -1.0f; int b1i = 0;
            #pragma unroll
            for (int j=0;j<8;++j){
                float v = ((msk >> j) & 1u) ? 0.0f : fabsf(h[j]);
                if (v > b1v){ b2v = b1v; b1v = v; b1i = lane*8 + j; }
                else if (v > b2v) b2v = v;
            }
            #pragma unroll
            for (int off=16; off>0; off>>=1){
                float ov1 = __shfl_down_sync(0xffffffffu, b1v, off);
                int   oi1 = __shfl_down_sync(0xffffffffu, b1i, off);
                float ov2 = __shfl_down_sync(0xffffffffu, b2v, off);
                if (ov1 > b1v || (ov1 == b1v && oi1 < b1i)){
                    b2v = fmaxf(b1v, ov2); b1v = ov1; b1i = oi1;
                } else {
                    b2v = fmaxf(b2v, ov1);
                }
            }
            float bestv = __shfl_sync(0xffffffffu, b1v, 0);
            float runv  = __shfl_sync(0xffffffffu, b2v, 0);
            int bi      = __shfl_sync(0xffffffffu, b1i, 0);
            idxs[k] = bi;
            if (bestv - runv < TAU_ARG) flagged = 1;
            if (lane == (bi >> 3)) msk |= 1u << (bi & 7);

            // G column: 2x LDG.128, coalesced
            {
                float4 ga = *(const float4*)&g_G[bi*256 + lane*8];
                float4 gb = *(const float4*)&g_G[bi*256 + lane*8 + 4];
                gcol[k][0]=ga.x; gcol[k][1]=ga.y; gcol[k][2]=ga.z; gcol[k][3]=ga.w;
                gcol[k][4]=gb.x; gcol[k][5]=gb.y; gcol[k][6]=gb.z; gcol[k][7]=gb.w;
            }

            if (k == 0){
                L[0][0] = 1.0f; rinv[0] = 1.0f;
            } else {
                float wv[4];
                #pragma unroll
                for (int r=0;r<4;++r){
                    if (r < k){
                        float v = g_G[idxs[r]*256 + bi];
                        #pragma unroll
                        for (int c2=0;c2<4;++c2) if (c2<r) v = __fmaf_rn(-L[r][c2], wv[c2], v);
                        wv[r] = v * rinv[r];
                    }
                }
                float ss = 0.f;
                #pragma unroll
                for (int c2=0;c2<4;++c2) if (c2<k) ss = __fadd_rn(ss, __fmul_rn(wv[c2], wv[c2]));
                #pragma unroll
                for (int c2=0;c2<4;++c2) if (c2<k) L[k][c2] = wv[c2];
                float rem = __fsub_rn(1.0f, ss);
                if (rem < TAU_CHOL) flagged = 1;
                rem = fmaxf(rem, 1e-12f);
                float rs = rsqrtf(rem);               // MUFU.RSQ (~1e-7 err, << TAU)
                L[k][k] = __fmul_rn(rem, rs);
                rinv[k] = rs;
            }
            // hbI = hb at atom bi (predicated select + shfl from owner lane)
            {
                int jsel = bi & 7;
                float v = hb[0];
                #pragma unroll
                for (int j=1;j<8;++j) if (jsel == j) v = hb[j];
                hbI[k] = __shfl_sync(0xffffffffu, v, bi >> 3);
            }

            float y[4];
            #pragma unroll
            for (int r=0;r<4;++r) if (r<=k){
                float v = hbI[r];
                #pragma unroll
                for (int c2=0;c2<4;++c2) if (c2<r) v = __fmaf_rn(-L[r][c2], y[c2], v);
                y[r] = v * rinv[r];
            }
            #pragma unroll
            for (int r=3;r>=0;--r) if (r<=k){
                float v = y[r];
                #pragma unroll
                for (int c2=0;c2<4;++c2) if (c2>r && c2<=k) v = __fmaf_rn(-L[c2][r], xs[c2], v);
                xs[r] = v * rinv[r];
            }

            if (k < 3){
                #pragma unroll
                for (int j=0;j<8;++j){
                    float beta = 0.f;
                    #pragma unroll
                    for (int q2=0;q2<4;++q2)
                        if (q2<=k) beta = __fmaf_rn(xs[q2], gcol[q2][j], beta);
                    h[j] = __fsub_rn(hb[j], beta);
                }
            }
        }

        // quantize (LUT decode) + reconstruct
        float q[4];
        #pragma unroll
        for (int k=0;k<4;++k) q[k] = mu_law_q_flag(xs[k], flagged);
        float r0 = 0.f, r1 = 0.f;
        #pragma unroll
        for (int k=0;k<4;++k){
            r0 = __fmaf_rn(q[k], g_DnT[idxs[k]*64 + lane],      r0);
            r1 = __fmaf_rn(q[k], g_DnT[idxs[k]*64 + lane + 32], r1);
        }
        R_s[lane*65 + sig]      = r0;
        R_s[(lane+32)*65 + sig] = r1;

        if (lane == 0){
            int gsig = blk*64 + sig;
            flag_s[sig] = flagged;
            g_fixloss[gsig] = 0.0f;
            if (flagged){
                int pos = atomicAdd(&g_qcount, 1);
                g_queue[pos] = gsig;
            }
        }
    }
    __syncthreads();

    // z_q write + loss (flagged signals excluded; fixed by k_fix)
    float lsum = 0.f;
    const int p  = t & 63;
    const int fl = flag_s[p];
    #pragma unroll
    for (int k = 0; k < 8; ++k){
        int idx = t + k*512;
        int c = idx >> 6;
        float x = X_s[idx];
        float r = R_s[c*65 + p];
        float d = __fsub_rn(r, x);
        if (fl){ dst[c*4096 + p] = x; }
        else   { dst[c*4096 + p] = __fadd_rn(x, d); lsum = __fmaf_rn(d, d, lsum); }
    }
    #pragma unroll
    for (int off=16; off>0; off>>=1) lsum += __shfl_down_sync(0xffffffffu, lsum, off);
    if (lane == 0) red[w] = lsum;
    __syncthreads();
    if (t == 0){
        float s = 0.f;
        #pragma unroll
        for (int w2=0; w2<16; ++w2) s += red[w2];
        g_partial[blk] = s;
    }
}

// ---------------- fp64 exact re-solve for flagged signals ----------------
__global__ void __launch_bounds__(256) k_fix(const float* __restrict__ z_e,
                                             float* __restrict__ out){
    __shared__ double xsh[8][64];
    const int lane = threadIdx.x & 31, wy = threadIdx.x >> 5;
    const int nwarps = gridDim.x * 8;
    const int w = blockIdx.x*8 + wy;
    const int cnt = g_qcount;
    const double INVD = 1.0 / log1p(50.0);

    for (int qi = w; qi < cnt; qi += nwarps){
        int gsig = g_queue[qi];
        int b = gsig >> 12, sp = gsig & 4095;
        const float* xp = z_e + (size_t)b*262144 + sp;
        float x0 = xp[(size_t)lane*4096], x1 = xp[(size_t)(lane+32)*4096];
        xsh[wy][lane] = (double)x0; xsh[wy][lane+32] = (double)x1;
        __syncwarp();

        // fp64 H, 4-way split accumulation (chain 16 deep; decision-safe)
        double hb64[8], h64[8];
        #pragma unroll
        for (int j=0;j<8;++j){
            int a = j*32 + lane;
            double s0 = 0.0, s1 = 0.0, s2 = 0.0, s3 = 0.0;
            #pragma unroll
            for (int c = 0; c < 16; ++c){
                s0 = fma(g_Dn64[(4*c  )*NUM_A + a], xsh[wy][4*c  ], s0);
                s1 = fma(g_Dn64[(4*c+1)*NUM_A + a], xsh[wy][4*c+1], s1);
                s2 = fma(g_Dn64[(4*c+2)*NUM_A + a], xsh[wy][4*c+2], s2);
                s3 = fma(g_Dn64[(4*c+3)*NUM_A + a], xsh[wy][4*c+3], s3);
            }
            hb64[j] = (s0 + s1) + (s2 + s3); h64[j] = hb64[j];
        }

        int idxs[4]; double L[4][4], Linv[4], xs[4], hbI[4];
        #pragma unroll
        for (int k = 0; k < 4; ++k){
            double best = -1.0; int bi = 0;
            #pragma unroll
            for (int j=0;j<8;++j){
                int a = j*32 + lane;
                bool sel = false;
                #pragma unroll
                for (int q2=0;q2<4;++q2) if (q2<k && idxs[q2]==a) sel = true;
                double v = sel ? 0.0 : fabs(h64[j]);
                if (v > best || (v == best && a < bi)){ best = v; bi = a; }
            }
            #pragma unroll
            for (int off=16; off>0; off>>=1){
                double ov = __shfl_down_sync(0xffffffffu, best, off);
                int    oi = __shfl_down_sync(0xffffffffu, bi,   off);
                if (ov > best || (ov == best && oi < bi)){ best = ov; bi = oi; }
            }
            bi = __shfl_sync(0xffffffffu, bi, 0);
            idxs[k] = bi;

            if (k == 0){
                L[0][0] = 1.0; Linv[0] = 1.0;
            } else {
                double wv[4];
                #pragma unroll
                for (int r=0;r<4;++r){
                    if (r < k){
                        double v = g_G64[idxs[r]*NUM_A + bi];
                        #pragma unroll
                        for (int c2=0;c2<4;++c2) if (c2<r) v = fma(-L[r][c2], wv[c2], v);
                        wv[r] = v * Linv[r];
                    }
                }
                double ss = 0.0;
                #pragma unroll
                for (int c2=0;c2<4;++c2) if (c2<k) ss = fma(wv[c2], wv[c2], ss);
                #pragma unroll
                for (int c2=0;c2<4;++c2) if (c2<k) L[k][c2] = wv[c2];
                L[k][k] = sqrt(fmax(1.0 - ss, 1e-12));
                Linv[k] = 1.0 / L[k][k];
            }
            {
                int jsel = bi >> 5;
                double v = hb64[0];
                #pragma unroll
                for (int j=1;j<8;++j) if (jsel == j) v = hb64[j];
                hbI[k] = __shfl_sync(0xffffffffu, v, bi & 31);
            }

            double y[4];
            #pragma unroll
            for (int r=0;r<4;++r) if (r<=k){
                double v = hbI[r];
                #pragma unroll
                for (int c2=0;c2<4;++c2) if (c2<r) v = fma(-L[r][c2], y[c2], v);
                y[r] = v * Linv[r];
            }
            #pragma unroll
            for (int r=3;r>=0;--r) if (r<=k){
                double v = y[r];
                #pragma unroll
                for (int c2=0;c2<4;++c2) if (c2>r && c2<=k) v = fma(-L[c2][r], xs[c2], v);
                xs[r] = v * Linv[r];
            }

            if (k < 3){
                #pragma unroll
                for (int j=0;j<8;++j){
                    int a = j*32 + lane;
                    double beta = 0.0;
                    #pragma unroll
                    for (int q2=0;q2<4;++q2)
                        if (q2<=k) beta = fma(xs[q2], g_G64[idxs[q2]*NUM_A + a], beta);
                    h64[j] = hb64[j] - beta;
                }
            }
        }

        float r0 = 0.f, r1 = 0.f;
        #pragma unroll
        for (int k=0;k<4;++k){
            double v = xs[k];
            double cl = fmin(fmax(v, -3.0), 3.0);
            double c  = cl / 3.0;
            double enc = copysign(log1p(fabs(c)*50.0) * INVD, c);
            double scaled = (enc + 1.0) * 7.5;
            int bq = (int)rint(scaled);
            bq = max(0, min(15, bq));
            float qk = g_dec[bq];
            r0 = __fmaf_rn(qk, g_DnT[idxs[k]*64 + lane],      r0);
            r1 = __fmaf_rn(qk, g_DnT[idxs[k]*64 + lane + 32], r1);
        }
        float d0 = __fsub_rn(r0, x0), d1 = __fsub_rn(r1, x1);
        out[(size_t)b*262144 + (size_t)lane*4096 + sp]      = __fadd_rn(x0, d0);
        out[(size_t)b*262144 + (size_t)(lane+32)*4096 + sp] = __fadd_rn(x1, d1);
        float ls = __fmaf_rn(d0, d0, __fmul_rn(d1, d1));
        #pragma unroll
        for (int off=16; off>0; off>>=1) ls += __shfl_down_sync(0xffffffffu, ls, off);
        if (lane == 0) g_fixloss[gsig] = ls;
        __syncwarp();
    }
}

// ---------------- deterministic parallel fixloss reduction ----------------
__global__ void k_fixred(){
    __shared__ float red[256];
    int base = blockIdx.x * 256;
    red[threadIdx.x] = g_fixloss[base + threadIdx.x];
    __syncthreads();
    for (int o = 128; o > 0; o >>= 1){
        if (threadIdx.x < o) red[threadIdx.x] += red[threadIdx.x + o];
        __syncthreads();
    }
    if (threadIdx.x == 0) g_partial2[blockIdx.x] = red[0];
}

// ---------------- finalize ----------------
__global__ void k_final(float* __restrict__ out, int out_size){
    __shared__ float red[256];
    float s = 0.f;
    for (int i = threadIdx.x; i < NBLOCKS; i += 256) s += g_partial[i];
    for (int i = threadIdx.x; i < 512; i += 256) s += g_partial2[i];
    red[threadIdx.x] = s;
    __syncthreads();
    for (int o = 128; o > 0; o >>= 1){
        if (threadIdx.x < o) red[threadIdx.x] += red[threadIdx.x + o];
        __syncthreads();
    }
    if (threadIdx.x == 0 && out_size > NELEM)
        out[NELEM] = 1.25f * red[0] / (float)NELEM;
}

// ---------------- launch ----------------
extern "C" void kernel_launch(void* const* d_in, const int* in_sizes, int n_in,
                              void* d_out, int out_size){
    const float* z_e  = (const float*)d_in[0];
    const float* dict = (const float*)d_in[1];
    float* out = (float*)d_out;

    cudaFuncSetAttribute(k_main, cudaFuncAttributeMaxDynamicSharedMemorySize, SM_BYTES);

    k_normalize<<<16, 256>>>(dict);
    k_gram<<<256, 256>>>();
    k_main<<<NBLOCKS, 512, SM_BYTES>>>(z_e, out);
    k_fix<<<296, 256>>>(z_e, out);
    k_fixred<<<512, 256>>>();
    k_final<<<1, 256>>>(out, out_size);
}

// round 16
// speedup vs baseline: 3.5468x; 1.0370x over previous
#include <cuda_runtime.h>
#include <math.h>

#define NUM_A 256
#define DIM 64
#define NSIG_TOTAL (32*64*64)
#define NBLOCKS (NSIG_TOTAL/64)      // 2048
#define NELEM 8388608

#define INV_LOG1P_MU 0.25433462858092786f
#define TAU_ARG  5e-5f
#define TAU_BIN  2e-4f
#define TAU_CHOL 3e-3f

// device-global scratch (no allocation allowed)
__device__ float  g_Dn[DIM*NUM_A];     // [c][a]
__device__ float  g_DnT[NUM_A*DIM];    // [a][c]
__device__ float  g_G[NUM_A*NUM_A];
__device__ double g_Dn64[DIM*NUM_A];
__device__ double g_G64[NUM_A*NUM_A];
__device__ float  g_dec[16];           // mu-law decode LUT
__device__ float  g_partial[NBLOCKS];
__device__ float  g_partial2[512];
__device__ float  g_fixloss[NSIG_TOTAL];
__device__ int    g_qcount;
__device__ int    g_queue[NSIG_TOTAL];

// ---------------- f32x2 helpers ----------------
#define FMA2(d, a, b, c) asm("fma.rn.f32x2 %0, %1, %2, %3;" : "=l"(d) : "l"(a), "l"(b), "l"(c))
#define PACKDUP(out, f)  asm("mov.b64 %0, {%1, %1};" : "=l"(out) : "r"(__float_as_uint(f)))

// ---------------- prep (16-way parallel over c-chunks) ----------------
__global__ void k_normalize(const float* __restrict__ dict){
    int a = threadIdx.x;
    if (blockIdx.x == 0 && a == 0){
        g_qcount = 0;
        const double INVD = 1.0 / log1p(50.0);
        #pragma unroll
        for (int b = 0; b < 16; ++b){
            double z = (double)b * (2.0/15.0) - 1.0;
            g_dec[b] = (float)copysign(expm1(fabs(z)/INVD)/50.0*3.0, z);
        }
    }
    float s = 0.f;  double s64 = 0.0;
    #pragma unroll
    for (int c = 0; c < DIM; ++c){
        float v = dict[c*NUM_A + a];
        s   = __fadd_rn(s, __fmul_rn(v, v));
        s64 = fma((double)v, (double)v, s64);
    }
    float  den   = fmaxf(__fsqrt_rn(s), 1e-10f);
    double den64 = fmax(sqrt(s64), 1e-10);
    int c0 = blockIdx.x * 4;
    #pragma unroll
    for (int cc = 0; cc < 4; ++cc){
        int c = c0 + cc;
        float v = __fdiv_rn(dict[c*NUM_A + a], den);
        g_Dn[c*NUM_A + a]  = v;
        g_DnT[a*DIM + c]   = v;
        g_Dn64[c*NUM_A + a] = (double)dict[c*NUM_A + a] / den64;
    }
}

__global__ void k_gram(){
    __shared__ float  di[DIM];
    __shared__ double di64[DIM];
    int i = blockIdx.x, j = threadIdx.x;
    if (j < DIM){ di[j] = g_DnT[i*DIM + j]; di64[j] = g_Dn64[j*NUM_A + i]; }
    __syncthreads();
    float s = 0.f;  double s64 = 0.0;
    #pragma unroll
    for (int c = 0; c < DIM; ++c){
        s   = __fmaf_rn(di[c], g_Dn[c*NUM_A + j], s);
        s64 = fma(di64[c], g_Dn64[c*NUM_A + j], s64);
    }
    g_G[i*NUM_A + j]   = s;
    g_G64[i*NUM_A + j] = s64;
}

// ---------------- mu-law (fast fp32 encode + LUT decode, boundary flag) -----
__device__ __forceinline__ float mu_law_q_flag(float v, int &flag){
    float cl = fminf(fmaxf(v, -3.0f), 3.0f);
    float c  = __fmul_rn(cl, 0.3333333432674408f);
    float enc = copysignf(__fmul_rn(log1pf(__fmul_rn(fabsf(c), 50.0f)), INV_LOG1P_MU), c);
    float scaled = __fmul_rn(__fadd_rn(enc, 1.0f), 7.5f);
    float fb = rintf(scaled);
    if (0.5f - fabsf(scaled - fb) < TAU_BIN) flag = 1;
    int b = (int)fb;
    b = max(0, min(15, b));
    return g_dec[b];
}

// ---------------- main fused kernel ----------------
// smem floats: Dn_s [64][256] @0 (16384), X_s [64][64] @16384 (4096),
//              H_s [64][260]  @20480 (16640), R_s [64][65] @37120 (4160).
// Total 41280 floats = 165120 B.  (HS=260: divisible by 4 so every
// H_s[sig*HS + lane*8] float4 access is 16B-aligned; 260 % 32 = 4 gives
// per-sig bank rotation.)
#define SM_DN 0
#define SM_X  16384
#define SM_H  20480
#define SM_R  37120
#define HS    260
#define SM_FLOATS 41280
#define SM_BYTES (SM_FLOATS*4)

__global__ void __launch_bounds__(512,1) k_main(const float* __restrict__ z_e,
                                               float* __restrict__ out){
    extern __shared__ float S[];
    float* Dn_s = S + SM_DN;
    float* X_s  = S + SM_X;
    float* H_s  = S + SM_H;
    float* R_s  = S + SM_R;
    __shared__ int flag_s[64];
    __shared__ float red[16];

    const int t    = threadIdx.x;
    const int w    = t >> 5;
    const int lane = t & 31;
    const int blk  = blockIdx.x;
    const int b    = blk >> 6;
    const int p0   = (blk & 63) << 6;
    const float* src = z_e + (size_t)b*262144 + p0;
    float*       dst = out + (size_t)b*262144 + p0;

    // --- load Dn tile (plain layout; GEMM reads it as warp-uniform broadcast) ---
    {
        const float4* g0 = (const float4*)g_Dn;
        float4*       s0 = (float4*)Dn_s;
        #pragma unroll
        for (int k = 0; k < 8; ++k) s0[t + k*512] = g0[t + k*512];
    }
    // --- load X tile: X_s[c][p] ---
    {
        float4* xd = (float4*)X_s;
        #pragma unroll
        for (int k = 0; k < 2; ++k){
            int idx4 = t + k*512;
            int c = idx4 >> 4, p4 = idx4 & 15;
            xd[idx4] = *(const float4*)(src + c*4096 + p4*4);
        }
    }
    __syncthreads();

    // --- atom-sliced GEMM: warp w owns atoms w*16..w*16+15, lane owns signals
    //     (lane, lane+32). acc2[si][ap] packs H[sig][w*16+2ap (+1)].
    //     Each H element: single lane, ascending-c, per-half IEEE FMA ->
    //     H bits identical to all previous rounds. ---
    {
        unsigned long long acc2[2][8];
        #pragma unroll
        for (int si=0; si<2; ++si)
            #pragma unroll
            for (int ap=0; ap<8; ++ap) acc2[si][ap] = 0ULL;
        #pragma unroll 2
        for (int c = 0; c < 64; ++c){
            const ulonglong2* dp = (const ulonglong2*)&Dn_s[c*256 + w*16];
            ulonglong2 q0 = dp[0], q1 = dp[1], q2 = dp[2], q3 = dp[3];
            unsigned long long d[8] = {q0.x,q0.y,q1.x,q1.y,q2.x,q2.y,q3.x,q3.y};
            float x0 = X_s[c*64 + lane];
            float x1 = X_s[c*64 + lane + 32];
            unsigned long long xd0, xd1;
            PACKDUP(xd0, x0); PACKDUP(xd1, x1);
            #pragma unroll
            for (int ap=0; ap<8; ++ap){
                FMA2(acc2[0][ap], xd0, d[ap], acc2[0][ap]);
                FMA2(acc2[1][ap], xd1, d[ap], acc2[1][ap]);
            }
        }
        // store H to smem: H_s[sig][a], row stride 260 (8B stores, aligned)
        #pragma unroll
        for (int ap=0; ap<8; ++ap){
            *(unsigned long long*)&H_s[lane*HS      + w*16 + 2*ap] = acc2[0][ap];
            *(unsigned long long*)&H_s[(lane+32)*HS + w*16 + 2*ap] = acc2[1][ap];
        }
    }
    __syncthreads();

    // --- OMP per signal (warp w -> signals w*4..w*4+3); atom a = lane*8 + j ---
    for (int i = 0; i < 4; ++i){
        const int sig = w*4 + i;
        float hb[8], h[8];
        {
            float4 ha = *(const float4*)&H_s[sig*HS + lane*8];
            float4 hc = *(const float4*)&H_s[sig*HS + lane*8 + 4];
            hb[0]=ha.x; hb[1]=ha.y; hb[2]=ha.z; hb[3]=ha.w;
            hb[4]=hc.x; hb[5]=hc.y; hb[6]=hc.z; hb[7]=hc.w;
            #pragma unroll
            for (int j=0;j<8;++j) h[j] = hb[j];
        }

        int   idxs[4];
        float L[4][4];
        float rinv[4];
        float hbI[4];
        float xs[4];
        float gcol[4][8];
        int   flagged = 0;
        unsigned int msk = 0;

        #pragma unroll
        for (int k = 0; k < 4; ++k){
            // single-pass top-2 masked argmax of |h|
            float b1v = -1.0f, b2v = -1.0f; int b1i = 0;
            #pragma unroll
            for (int j=0;j<8;++j){
                float v = ((msk >> j) & 1u) ? 0.0f : fabsf(h[j]);
                if (v > b1v){ b2v = b1v; b1v = v; b1i = lane*8 + j; }
                else if (v > b2v) b2v = v;
            }
            #pragma unroll
            for (int off=16; off>0; off>>=1){
                float ov1 = __shfl_down_sync(0xffffffffu, b1v, off);
                int   oi1 = __shfl_down_sync(0xffffffffu, b1i, off);
                float ov2 = __shfl_down_sync(0xffffffffu, b2v, off);
                if (ov1 > b1v || (ov1 == b1v && oi1 < b1i)){
                    b2v = fmaxf(b1v, ov2); b1v = ov1; b1i = oi1;
                } else {
                    b2v = fmaxf(b2v, ov1);
                }
            }
            float bestv = __shfl_sync(0xffffffffu, b1v, 0);
            float runv  = __shfl_sync(0xffffffffu, b2v, 0);
            int bi      = __shfl_sync(0xffffffffu, b1i, 0);
            idxs[k] = bi;
            if (bestv - runv < TAU_ARG) flagged = 1;
            if (lane == (bi >> 3)) msk |= 1u << (bi & 7);

            // G column: 2x LDG.128, coalesced
            {
                float4 ga = *(const float4*)&g_G[bi*256 + lane*8];
                float4 gb = *(const float4*)&g_G[bi*256 + lane*8 + 4];
                gcol[k][0]=ga.x; gcol[k][1]=ga.y; gcol[k][2]=ga.z; gcol[k][3]=ga.w;
                gcol[k][4]=gb.x; gcol[k][5]=gb.y; gcol[k][6]=gb.z; gcol[k][7]=gb.w;
            }

            if (k == 0){
                L[0][0] = 1.0f; rinv[0] = 1.0f;
            } else {
                float wv[4];
                #pragma unroll
                for (int r=0;r<4;++r){
                    if (r < k){
                        float v = g_G[idxs[r]*256 + bi];
                        #pragma unroll
                        for (int c2=0;c2<4;++c2) if (c2<r) v = __fmaf_rn(-L[r][c2], wv[c2], v);
                        wv[r] = v * rinv[r];
                    }
                }
                float ss = 0.f;
                #pragma unroll
                for (int c2=0;c2<4;++c2) if (c2<k) ss = __fadd_rn(ss, __fmul_rn(wv[c2], wv[c2]));
                #pragma unroll
                for (int c2=0;c2<4;++c2) if (c2<k) L[k][c2] = wv[c2];
                float rem = __fsub_rn(1.0f, ss);
                if (rem < TAU_CHOL) flagged = 1;
                rem = fmaxf(rem, 1e-12f);
                float rs = rsqrtf(rem);
                L[k][k] = __fmul_rn(rem, rs);
                rinv[k] = rs;
            }
            hbI[k] = H_s[sig*HS + bi];          // broadcast LDS

            float y[4];
            #pragma unroll
            for (int r=0;r<4;++r) if (r<=k){
                float v = hbI[r];
                #pragma unroll
                for (int c2=0;c2<4;++c2) if (c2<r) v = __fmaf_rn(-L[r][c2], y[c2], v);
                y[r] = v * rinv[r];
            }
            #pragma unroll
            for (int r=3;r>=0;--r) if (r<=k){
                float v = y[r];
                #pragma unroll
                for (int c2=0;c2<4;++c2) if (c2>r && c2<=k) v = __fmaf_rn(-L[c2][r], xs[c2], v);
                xs[r] = v * rinv[r];
            }

            if (k < 3){
                #pragma unroll
                for (int j=0;j<8;++j){
                    float beta = 0.f;
                    #pragma unroll
                    for (int q2=0;q2<4;++q2)
                        if (q2<=k) beta = __fmaf_rn(xs[q2], gcol[q2][j], beta);
                    h[j] = __fsub_rn(hb[j], beta);
                }
            }
        }

        // quantize (LUT decode) + reconstruct
        float q[4];
        #pragma unroll
        for (int k=0;k<4;++k) q[k] = mu_law_q_flag(xs[k], flagged);
        float r0 = 0.f, r1 = 0.f;
        #pragma unroll
        for (int k=0;k<4;++k){
            r0 = __fmaf_rn(q[k], g_DnT[idxs[k]*64 + lane],      r0);
            r1 = __fmaf_rn(q[k], g_DnT[idxs[k]*64 + lane + 32], r1);
        }
        R_s[lane*65 + sig]      = r0;
        R_s[(lane+32)*65 + sig] = r1;

        if (lane == 0){
            int gsig = blk*64 + sig;
            flag_s[sig] = flagged;
            g_fixloss[gsig] = 0.0f;
            if (flagged){
                int pos = atomicAdd(&g_qcount, 1);
                g_queue[pos] = gsig;
            }
        }
    }
    __syncthreads();

    // z_q write + loss (flagged signals excluded; fixed by k_fix)
    float lsum = 0.f;
    const int p  = t & 63;
    const int fl = flag_s[p];
    #pragma unroll
    for (int k = 0; k < 8; ++k){
        int idx = t + k*512;
        int c = idx >> 6;
        float x = X_s[idx];
        float r = R_s[c*65 + p];
        float d = __fsub_rn(r, x);
        if (fl){ dst[c*4096 + p] = x; }
        else   { dst[c*4096 + p] = __fadd_rn(x, d); lsum = __fmaf_rn(d, d, lsum); }
    }
    #pragma unroll
    for (int off=16; off>0; off>>=1) lsum += __shfl_down_sync(0xffffffffu, lsum, off);
    if (lane == 0) red[w] = lsum;
    __syncthreads();
    if (t == 0){
        float s = 0.f;
        #pragma unroll
        for (int w2=0; w2<16; ++w2) s += red[w2];
        g_partial[blk] = s;
    }
}

// ---------------- fp64 exact re-solve for flagged signals ----------------
__global__ void __launch_bounds__(256) k_fix(const float* __restrict__ z_e,
                                             float* __restrict__ out){
    __shared__ double xsh[8][64];
    const int lane = threadIdx.x & 31, wy = threadIdx.x >> 5;
    const int nwarps = gridDim.x * 8;
    const int w = blockIdx.x*8 + wy;
    const int cnt = g_qcount;
    const double INVD = 1.0 / log1p(50.0);

    for (int qi = w; qi < cnt; qi += nwarps){
        int gsig = g_queue[qi];
        int b = gsig >> 12, sp = gsig & 4095;
        const float* xp = z_e + (size_t)b*262144 + sp;
        float x0 = xp[(size_t)lane*4096], x1 = xp[(size_t)(lane+32)*4096];
        xsh[wy][lane] = (double)x0; xsh[wy][lane+32] = (double)x1;
        __syncwarp();

        double hb64[8], h64[8];
        #pragma unroll
        for (int j=0;j<8;++j){
            int a = j*32 + lane;
            double s0 = 0.0, s1 = 0.0, s2 = 0.0, s3 = 0.0;
            #pragma unroll
            for (int c = 0; c < 16; ++c){
                s0 = fma(g_Dn64[(4*c  )*NUM_A + a], xsh[wy][4*c  ], s0);
                s1 = fma(g_Dn64[(4*c+1)*NUM_A + a], xsh[wy][4*c+1], s1);
                s2 = fma(g_Dn64[(4*c+2)*NUM_A + a], xsh[wy][4*c+2], s2);
                s3 = fma(g_Dn64[(4*c+3)*NUM_A + a], xsh[wy][4*c+3], s3);
            }
            hb64[j] = (s0 + s1) + (s2 + s3); h64[j] = hb64[j];
        }

        int idxs[4]; double L[4][4], Linv[4], xs[4], hbI[4];
        #pragma unroll
        for (int k = 0; k < 4; ++k){
            double best = -1.0; int bi = 0;
            #pragma unroll
            for (int j=0;j<8;++j){
                int a = j*32 + lane;
                bool sel = false;
                #pragma unroll
                for (int q2=0;q2<4;++q2) if (q2<k && idxs[q2]==a) sel = true;
                double v = sel ? 0.0 : fabs(h64[j]);
                if (v > best || (v == best && a < bi)){ best = v; bi = a; }
            }
            #pragma unroll
            for (int off=16; off>0; off>>=1){
                double ov = __shfl_down_sync(0xffffffffu, best, off);
                int    oi = __shfl_down_sync(0xffffffffu, bi,   off);
                if (ov > best || (ov == best && oi < bi)){ best = ov; bi = oi; }
            }
            bi = __shfl_sync(0xffffffffu, bi, 0);
            idxs[k] = bi;

            if (k == 0){
                L[0][0] = 1.0; Linv[0] = 1.0;
            } else {
                double wv[4];
                #pragma unroll
                for (int r=0;r<4;++r){
                    if (r < k){
                        double v = g_G64[idxs[r]*NUM_A + bi];
                        #pragma unroll
                        for (int c2=0;c2<4;++c2) if (c2<r) v = fma(-L[r][c2], wv[c2], v);
                        wv[r] = v * Linv[r];
                    }
                }
                double ss = 0.0;
                #pragma unroll
                for (int c2=0;c2<4;++c2) if (c2<k) ss = fma(wv[c2], wv[c2], ss);
                #pragma unroll
                for (int c2=0;c2<4;++c2) if (c2<k) L[k][c2] = wv[c2];
                L[k][k] = sqrt(fmax(1.0 - ss, 1e-12));
                Linv[k] = 1.0 / L[k][k];
            }
            {
                int jsel = bi >> 5;
                double v = hb64[0];
                #pragma unroll
                for (int j=1;j<8;++j) if (jsel == j) v = hb64[j];
                hbI[k] = __shfl_sync(0xffffffffu, v, bi & 31);
            }

            double y[4];
            #pragma unroll
            for (int r=0;r<4;++r) if (r<=k){
                double v = hbI[r];
                #pragma unroll
                for (int c2=0;c2<4;++c2) if (c2<r) v = fma(-L[r][c2], y[c2], v);
                y[r] = v * Linv[r];
            }
            #pragma unroll
            for (int r=3;r>=0;--r) if (r<=k){
                double v = y[r];
                #pragma unroll
                for (int c2=0;c2<4;++c2) if (c2>r && c2<=k) v = fma(-L[c2][r], xs[c2], v);
                xs[r] = v * Linv[r];
            }

            if (k < 3){
                #pragma unroll
                for (int j=0;j<8;++j){
                    int a = j*32 + lane;
                    double beta = 0.0;
                    #pragma unroll
                    for (int q2=0;q2<4;++q2)
                        if (q2<=k) beta = fma(xs[q2], g_G64[idxs[q2]*NUM_A + a], beta);
                    h64[j] = hb64[j] - beta;
                }
            }
        }

        float r0 = 0.f, r1 = 0.f;
        #pragma unroll
        for (int k=0;k<4;++k){
            double v = xs[k];
            double cl = fmin(fmax(v, -3.0), 3.0);
            double c  = cl / 3.0;
            double enc = copysign(log1p(fabs(c)*50.0) * INVD, c);
            double scaled = (enc + 1.0) * 7.5;
            int bq = (int)rint(scaled);
            bq = max(0, min(15, bq));
            float qk = g_dec[bq];
            r0 = __fmaf_rn(qk, g_DnT[idxs[k]*64 + lane],      r0);
            r1 = __fmaf_rn(qk, g_DnT[idxs[k]*64 + lane + 32], r1);
        }
        float d0 = __fsub_rn(r0, x0), d1 = __fsub_rn(r1, x1);
        out[(size_t)b*262144 + (size_t)lane*4096 + sp]      = __fadd_rn(x0, d0);
        out[(size_t)b*262144 + (size_t)(lane+32)*4096 + sp] = __fadd_rn(x1, d1);
        float ls = __fmaf_rn(d0, d0, __fmul_rn(d1, d1));
        #pragma unroll
        for (int off=16; off>0; off>>=1) ls += __shfl_down_sync(0xffffffffu, ls, off);
        if (lane == 0) g_fixloss[gsig] = ls;
        __syncwarp();
    }
}

// ---------------- deterministic parallel fixloss reduction ----------------
__global__ void k_fixred(){
    __shared__ float red[256];
    int base = blockIdx.x * 256;
    red[threadIdx.x] = g_fixloss[base + threadIdx.x];
    __syncthreads();
    for (int o = 128; o > 0; o >>= 1){
        if (threadIdx.x < o) red[threadIdx.x] += red[threadIdx.x + o];
        __syncthreads();
    }
    if (threadIdx.x == 0) g_partial2[blockIdx.x] = red[0];
}

// ---------------- finalize ----------------
__global__ void k_final(float* __restrict__ out, int out_size){
    __shared__ float red[256];
    float s = 0.f;
    for (int i = threadIdx.x; i < NBLOCKS; i += 256) s += g_partial[i];
    for (int i = threadIdx.x; i < 512; i += 256) s += g_partial2[i];
    red[threadIdx.x] = s;
    __syncthreads();
    for (int o = 128; o > 0; o >>= 1){
        if (threadIdx.x < o) red[threadIdx.x] += red[threadIdx.x + o];
        __syncthreads();
    }
    if (threadIdx.x == 0 && out_size > NELEM)
        out[NELEM] = 1.25f * red[0] / (float)NELEM;
}

// ---------------- launch ----------------
extern "C" void kernel_launch(void* const* d_in, const int* in_sizes, int n_in,
                              void* d_out, int out_size){
    const float* z_e  = (const float*)d_in[0];
    const float* dict = (const float*)d_in[1];
    float* out = (float*)d_out;

    cudaFuncSetAttribute(k_main, cudaFuncAttributeMaxDynamicSharedMemorySize, SM_BYTES);

    k_normalize<<<16, 256>>>(dict);
    k_gram<<<256, 256>>>();
    k_main<<<NBLOCKS, 512, SM_BYTES>>>(z_e, out);
    k_fix<<<296, 256>>>(z_e, out);
    k_fixred<<<512, 256>>>();
    k_final<<<1, 256>>>(out, out_size);
}

// round 17
// speedup vs baseline: 3.8832x; 1.0948x over previous
#include <cuda_runtime.h>
#include <math.h>

#define NUM_A 256
#define DIM 64
#define NSIG_TOTAL (32*64*64)
#define NBLOCKS (NSIG_TOTAL/64)      // 2048
#define NELEM 8388608

#define INV_LOG1P_MU 0.25433462858092786f
#define TAU_ARG  5e-5f
#define TAU_BIN  2e-4f
#define TAU_CHOL 3e-3f

// device-global scratch (no allocation allowed)
__device__ float  g_Dn[DIM*NUM_A];     // [c][a]
__device__ float  g_DnT[NUM_A*DIM];    // [a][c]
__device__ float  g_G[NUM_A*NUM_A];
__device__ float2 g_Dn2[DIM*NUM_A];    // df64 split of Dn64 (hi, lo)
__device__ double g_Dn64[DIM*NUM_A];   // for k_gram only
__device__ double g_G64[NUM_A*NUM_A];
__device__ float  g_dec[16];           // mu-law decode LUT
__device__ float  g_partial[NBLOCKS];
__device__ float  g_partial2[512];
__device__ float  g_fixloss[NSIG_TOTAL];
__device__ int    g_qcount;
__device__ int    g_queue[NSIG_TOTAL];

// ---------------- f32x2 helpers ----------------
#define FMA2(d, a, b, c) asm("fma.rn.f32x2 %0, %1, %2, %3;" : "=l"(d) : "l"(a), "l"(b), "l"(c))
#define PACKDUP(out, f)  asm("mov.b64 %0, {%1, %1};" : "=l"(out) : "r"(__float_as_uint(f)))

// ---------------- prep (16-way parallel over c-chunks) ----------------
__global__ void k_normalize(const float* __restrict__ dict){
    int a = threadIdx.x;
    if (blockIdx.x == 0 && a == 0){
        g_qcount = 0;
        const double INVD = 1.0 / log1p(50.0);
        #pragma unroll
        for (int b = 0; b < 16; ++b){
            double z = (double)b * (2.0/15.0) - 1.0;
            g_dec[b] = (float)copysign(expm1(fabs(z)/INVD)/50.0*3.0, z);
        }
    }
    float s = 0.f;  double s64 = 0.0;
    #pragma unroll
    for (int c = 0; c < DIM; ++c){
        float v = dict[c*NUM_A + a];
        s   = __fadd_rn(s, __fmul_rn(v, v));
        s64 = fma((double)v, (double)v, s64);
    }
    float  den   = fmaxf(__fsqrt_rn(s), 1e-10f);
    double inv64 = 1.0 / fmax(sqrt(s64), 1e-10);
    int c0 = blockIdx.x * 4;
    #pragma unroll
    for (int cc = 0; cc < 4; ++cc){
        int c = c0 + cc;
        float v = __fdiv_rn(dict[c*NUM_A + a], den);
        g_Dn[c*NUM_A + a]  = v;
        g_DnT[a*DIM + c]   = v;
        double v64 = (double)dict[c*NUM_A + a] * inv64;
        g_Dn64[c*NUM_A + a] = v64;
        float hi = (float)v64;
        float lo = (float)(v64 - (double)hi);
        g_Dn2[c*NUM_A + a] = make_float2(hi, lo);
    }
}

__global__ void k_gram(){
    __shared__ float  di[DIM];
    __shared__ double di64[DIM];
    int i = blockIdx.x, j = threadIdx.x;
    if (j < DIM){ di[j] = g_DnT[i*DIM + j]; di64[j] = g_Dn64[j*NUM_A + i]; }
    __syncthreads();
    float s = 0.f;  double s64 = 0.0;
    #pragma unroll
    for (int c = 0; c < DIM; ++c){
        s   = __fmaf_rn(di[c], g_Dn[c*NUM_A + j], s);
        s64 = fma(di64[c], g_Dn64[c*NUM_A + j], s64);
    }
    g_G[i*NUM_A + j]   = s;
    g_G64[i*NUM_A + j] = s64;
}

// ---------------- mu-law (fast fp32 encode + LUT decode, boundary flag) -----
__device__ __forceinline__ float mu_law_q_flag(float v, int &flag){
    float cl = fminf(fmaxf(v, -3.0f), 3.0f);
    float c  = __fmul_rn(cl, 0.3333333432674408f);
    float enc = copysignf(__fmul_rn(log1pf(__fmul_rn(fabsf(c), 50.0f)), INV_LOG1P_MU), c);
    float scaled = __fmul_rn(__fadd_rn(enc, 1.0f), 7.5f);
    float fb = rintf(scaled);
    if (0.5f - fabsf(scaled - fb) < TAU_BIN) flag = 1;
    int b = (int)fb;
    b = max(0, min(15, b));
    return g_dec[b];
}

// ---------------- main fused kernel ----------------
// smem floats: Dn_s [64][256] @0 (16384), X_s [64][64] @16384 (4096),
//              H_s [64][260]  @20480 (16640), R_s [64][65] @37120 (4160).
#define SM_DN 0
#define SM_X  16384
#define SM_H  20480
#define SM_R  37120
#define HS    260
#define SM_FLOATS 41280
#define SM_BYTES (SM_FLOATS*4)

__global__ void __launch_bounds__(512,1) k_main(const float* __restrict__ z_e,
                                               float* __restrict__ out){
    extern __shared__ float S[];
    float* Dn_s = S + SM_DN;
    float* X_s  = S + SM_X;
    float* H_s  = S + SM_H;
    float* R_s  = S + SM_R;
    __shared__ int flag_s[64];
    __shared__ float red[16];

    const int t    = threadIdx.x;
    const int w    = t >> 5;
    const int lane = t & 31;
    const int blk  = blockIdx.x;
    const int b    = blk >> 6;
    const int p0   = (blk & 63) << 6;
    const float* src = z_e + (size_t)b*262144 + p0;
    float*       dst = out + (size_t)b*262144 + p0;

    // --- load Dn tile ---
    {
        const float4* g0 = (const float4*)g_Dn;
        float4*       s0 = (float4*)Dn_s;
        #pragma unroll
        for (int k = 0; k < 8; ++k) s0[t + k*512] = g0[t + k*512];
    }
    // --- load X tile ---
    {
        float4* xd = (float4*)X_s;
        #pragma unroll
        for (int k = 0; k < 2; ++k){
            int idx4 = t + k*512;
            int c = idx4 >> 4, p4 = idx4 & 15;
            xd[idx4] = *(const float4*)(src + c*4096 + p4*4);
        }
    }
    __syncthreads();

    // --- atom-sliced GEMM (bit-identical H) ---
    {
        unsigned long long acc2[2][8];
        #pragma unroll
        for (int si=0; si<2; ++si)
            #pragma unroll
            for (int ap=0; ap<8; ++ap) acc2[si][ap] = 0ULL;
        #pragma unroll 2
        for (int c = 0; c < 64; ++c){
            const ulonglong2* dp = (const ulonglong2*)&Dn_s[c*256 + w*16];
            ulonglong2 q0 = dp[0], q1 = dp[1], q2 = dp[2], q3 = dp[3];
            unsigned long long d[8] = {q0.x,q0.y,q1.x,q1.y,q2.x,q2.y,q3.x,q3.y};
            float x0 = X_s[c*64 + lane];
            float x1 = X_s[c*64 + lane + 32];
            unsigned long long xd0, xd1;
            PACKDUP(xd0, x0); PACKDUP(xd1, x1);
            #pragma unroll
            for (int ap=0; ap<8; ++ap){
                FMA2(acc2[0][ap], xd0, d[ap], acc2[0][ap]);
                FMA2(acc2[1][ap], xd1, d[ap], acc2[1][ap]);
            }
        }
        #pragma unroll
        for (int ap=0; ap<8; ++ap){
            *(unsigned long long*)&H_s[lane*HS      + w*16 + 2*ap] = acc2[0][ap];
            *(unsigned long long*)&H_s[(lane+32)*HS + w*16 + 2*ap] = acc2[1][ap];
        }
    }
    __syncthreads();

    // --- OMP per signal (warp w -> signals w*4..w*4+3); atom a = lane*8 + j ---
    for (int i = 0; i < 4; ++i){
        const int sig = w*4 + i;
        float hb[8], h[8];
        {
            float4 ha = *(const float4*)&H_s[sig*HS + lane*8];
            float4 hc = *(const float4*)&H_s[sig*HS + lane*8 + 4];
            hb[0]=ha.x; hb[1]=ha.y; hb[2]=ha.z; hb[3]=ha.w;
            hb[4]=hc.x; hb[5]=hc.y; hb[6]=hc.z; hb[7]=hc.w;
            #pragma unroll
            for (int j=0;j<8;++j) h[j] = hb[j];
        }

        int   idxs[4];
        float L[4][4];
        float rinv[4];
        float hbI[4];
        float xs[4];
        float gcol[4][8];
        int   flagged = 0;
        unsigned int msk = 0;

        #pragma unroll
        for (int k = 0; k < 4; ++k){
            // local top-2 masked argmax of |h| (strict > keeps lowest index)
            float b1v = -1.0f, b2v = -1.0f; int b1i = 0;
            #pragma unroll
            for (int j=0;j<8;++j){
                float v = ((msk >> j) & 1u) ? 0.0f : fabsf(h[j]);
                if (v > b1v){ b2v = b1v; b1v = v; b1i = lane*8 + j; }
                else if (v > b2v) b2v = v;
            }
            // warp combine via REDUX (|h| >= 0 -> uint-monotone float bits)
            unsigned ub = __reduce_max_sync(0xffffffffu, __float_as_uint(b1v));
            bool atbest = (__float_as_uint(b1v) == ub);
            unsigned bal = __ballot_sync(0xffffffffu, atbest);
            int bi = (int)__reduce_min_sync(0xffffffffu,
                        atbest ? (unsigned)b1i : 0xffffffffu);
            float cand = atbest ? b2v : b1v;
            unsigned ur = __reduce_max_sync(0xffffffffu, __float_as_uint(cand));
            float bestv = __uint_as_float(ub);
            float runv  = __uint_as_float(ur);
            if (__fsub_rn(bestv, runv) < TAU_ARG || __popc(bal) > 1) flagged = 1;
            idxs[k] = bi;
            if (lane == (bi >> 3)) msk |= 1u << (bi & 7);

            // G column: 2x LDG.128, coalesced
            {
                float4 ga = *(const float4*)&g_G[bi*256 + lane*8];
                float4 gb = *(const float4*)&g_G[bi*256 + lane*8 + 4];
                gcol[k][0]=ga.x; gcol[k][1]=ga.y; gcol[k][2]=ga.z; gcol[k][3]=ga.w;
                gcol[k][4]=gb.x; gcol[k][5]=gb.y; gcol[k][6]=gb.z; gcol[k][7]=gb.w;
            }

            if (k == 0){
                L[0][0] = 1.0f; rinv[0] = 1.0f;
            } else {
                float wv[4];
                #pragma unroll
                for (int r=0;r<4;++r){
                    if (r < k){
                        float v = g_G[idxs[r]*256 + bi];
                        #pragma unroll
                        for (int c2=0;c2<4;++c2) if (c2<r) v = __fmaf_rn(-L[r][c2], wv[c2], v);
                        wv[r] = v * rinv[r];
                    }
                }
                float ss = 0.f;
                #pragma unroll
                for (int c2=0;c2<4;++c2) if (c2<k) ss = __fadd_rn(ss, __fmul_rn(wv[c2], wv[c2]));
                #pragma unroll
                for (int c2=0;c2<4;++c2) if (c2<k) L[k][c2] = wv[c2];
                float rem = __fsub_rn(1.0f, ss);
                if (rem < TAU_CHOL) flagged = 1;
                rem = fmaxf(rem, 1e-12f);
                float rs = rsqrtf(rem);
                L[k][k] = __fmul_rn(rem, rs);
                rinv[k] = rs;
            }
            hbI[k] = H_s[sig*HS + bi];          // broadcast LDS

            float y[4];
            #pragma unroll
            for (int r=0;r<4;++r) if (r<=k){
                float v = hbI[r];
                #pragma unroll
                for (int c2=0;c2<4;++c2) if (c2<r) v = __fmaf_rn(-L[r][c2], y[c2], v);
                y[r] = v * rinv[r];
            }
            #pragma unroll
            for (int r=3;r>=0;--r) if (r<=k){
                float v = y[r];
                #pragma unroll
                for (int c2=0;c2<4;++c2) if (c2>r && c2<=k) v = __fmaf_rn(-L[c2][r], xs[c2], v);
                xs[r] = v * rinv[r];
            }

            if (k < 3){
                #pragma unroll
                for (int j=0;j<8;++j){
                    float beta = 0.f;
                    #pragma unroll
                    for (int q2=0;q2<4;++q2)
                        if (q2<=k) beta = __fmaf_rn(xs[q2], gcol[q2][j], beta);
                    h[j] = __fsub_rn(hb[j], beta);
                }
            }
        }

        // quantize (LUT decode) + reconstruct
        float q[4];
        #pragma unroll
        for (int k=0;k<4;++k) q[k] = mu_law_q_flag(xs[k], flagged);
        float r0 = 0.f, r1 = 0.f;
        #pragma unroll
        for (int k=0;k<4;++k){
            r0 = __fmaf_rn(q[k], g_DnT[idxs[k]*64 + lane],      r0);
            r1 = __fmaf_rn(q[k], g_DnT[idxs[k]*64 + lane + 32], r1);
        }
        R_s[lane*65 + sig]      = r0;
        R_s[(lane+32)*65 + sig] = r1;

        if (lane == 0){
            int gsig = blk*64 + sig;
            flag_s[sig] = flagged;
            g_fixloss[gsig] = 0.0f;
            if (flagged){
                int pos = atomicAdd(&g_qcount, 1);
                g_queue[pos] = gsig;
            }
        }
    }
    __syncthreads();

    // z_q write + loss (flagged signals excluded; fixed by k_fix)
    float lsum = 0.f;
    const int p  = t & 63;
    const int fl = flag_s[p];
    #pragma unroll
    for (int k = 0; k < 8; ++k){
        int idx = t + k*512;
        int c = idx >> 6;
        float x = X_s[idx];
        float r = R_s[c*65 + p];
        float d = __fsub_rn(r, x);
        if (fl){ dst[c*4096 + p] = x; }
        else   { dst[c*4096 + p] = __fadd_rn(x, d); lsum = __fmaf_rn(d, d, lsum); }
    }
    #pragma unroll
    for (int off=16; off>0; off>>=1) lsum += __shfl_down_sync(0xffffffffu, lsum, off);
    if (lane == 0) red[w] = lsum;
    __syncthreads();
    if (t == 0){
        float s = 0.f;
        #pragma unroll
        for (int w2=0; w2<16; ++w2) s += red[w2];
        g_partial[blk] = s;
    }
}

// ---------------- exact re-solve for flagged signals (df64 H, fp64 OMP) -----
__global__ void __launch_bounds__(256) k_fix(const float* __restrict__ z_e,
                                             float* __restrict__ out){
    __shared__ float xsh[8][64];
    const int lane = threadIdx.x & 31, wy = threadIdx.x >> 5;
    const int nwarps = gridDim.x * 8;
    const int w = blockIdx.x*8 + wy;
    const int cnt = g_qcount;
    const double INVD = 1.0 / log1p(50.0);

    for (int qi = w; qi < cnt; qi += nwarps){
        int gsig = g_queue[qi];
        int b = gsig >> 12, sp = gsig & 4095;
        const float* xp = z_e + (size_t)b*262144 + sp;
        float x0 = xp[(size_t)lane*4096], x1 = xp[(size_t)(lane+32)*4096];
        xsh[wy][lane] = x0; xsh[wy][lane+32] = x1;
        __syncwarp();

        // df64 H on the fp32 pipe: exact 2Prod + 2Sum accumulation.
        // Error ~1e-12 relative -> decisions truth-exact for any margin that matters.
        double hb64[8], h64[8];
        #pragma unroll
        for (int j=0;j<8;++j){
            int a = j*32 + lane;
            float sh = 0.f, sl = 0.f;
            #pragma unroll 8
            for (int c = 0; c < 64; ++c){
                float  x = xsh[wy][c];
                float2 d = g_Dn2[c*NUM_A + a];
                float ph = __fmul_rn(d.x, x);
                float pe = __fmaf_rn(d.x, x, -ph);     // exact product tail
                pe = __fmaf_rn(d.y, x, pe);            // + lo*x
                float tt = __fadd_rn(sh, ph);          // 2Sum
                float bb = __fsub_rn(tt, sh);
                float er = __fadd_rn(__fsub_rn(sh, __fsub_rn(tt, bb)),
                                     __fsub_rn(ph, bb));
                sh = tt;
                sl = __fadd_rn(sl, __fadd_rn(er, pe));
            }
            hb64[j] = (double)sh + (double)sl;
            h64[j]  = hb64[j];
        }

        int idxs[4]; double L[4][4], Linv[4], xs[4], hbI[4];
        #pragma unroll
        for (int k = 0; k < 4; ++k){
            double best = -1.0; int bi = 0;
            #pragma unroll
            for (int j=0;j<8;++j){
                int a = j*32 + lane;
                bool sel = false;
                #pragma unroll
                for (int q2=0;q2<4;++q2) if (q2<k && idxs[q2]==a) sel = true;
                double v = sel ? 0.0 : fabs(h64[j]);
                if (v > best || (v == best && a < bi)){ best = v; bi = a; }
            }
            #pragma unroll
            for (int off=16; off>0; off>>=1){
                double ov = __shfl_down_sync(0xffffffffu, best, off);
                int    oi = __shfl_down_sync(0xffffffffu, bi,   off);
                if (ov > best || (ov == best && oi < bi)){ best = ov; bi = oi; }
            }
            bi = __shfl_sync(0xffffffffu, bi, 0);
            idxs[k] = bi;

            if (k == 0){
                L[0][0] = 1.0; Linv[0] = 1.0;
            } else {
                double wv[4];
                #pragma unroll
                for (int r=0;r<4;++r){
                    if (r < k){
                        double v = g_G64[idxs[r]*NUM_A + bi];
                        #pragma unroll
                        for (int c2=0;c2<4;++c2) if (c2<r) v = fma(-L[r][c2], wv[c2], v);
                        wv[r] = v * Linv[r];
                    }
                }
                double ss = 0.0;
                #pragma unroll
                for (int c2=0;c2<4;++c2) if (c2<k) ss = fma(wv[c2], wv[c2], ss);
                #pragma unroll
                for (int c2=0;c2<4;++c2) if (c2<k) L[k][c2] = wv[c2];
                L[k][k] = sqrt(fmax(1.0 - ss, 1e-12));
                Linv[k] = 1.0 / L[k][k];
            }
            {
                int jsel = bi >> 5;
                double v = hb64[0];
                #pragma unroll
                for (int j=1;j<8;++j) if (jsel == j) v = hb64[j];
                hbI[k] = __shfl_sync(0xffffffffu, v, bi & 31);
            }

            double y[4];
            #pragma unroll
            for (int r=0;r<4;++r) if (r<=k){
                double v = hbI[r];
                #pragma unroll
                for (int c2=0;c2<4;++c2) if (c2<r) v = fma(-L[r][c2], y[c2], v);
                y[r] = v * Linv[r];
            }
            #pragma unroll
            for (int r=3;r>=0;--r) if (r<=k){
                double v = y[r];
                #pragma unroll
                for (int c2=0;c2<4;++c2) if (c2>r && c2<=k) v = fma(-L[c2][r], xs[c2], v);
                xs[r] = v * Linv[r];
            }

            if (k < 3){
                #pragma unroll
                for (int j=0;j<8;++j){
                    int a = j*32 + lane;
                    double beta = 0.0;
                    #pragma unroll
                    for (int q2=0;q2<4;++q2)
                        if (q2<=k) beta = fma(xs[q2], g_G64[idxs[q2]*NUM_A + a], beta);
                    h64[j] = hb64[j] - beta;
                }
            }
        }

        float r0 = 0.f, r1 = 0.f;
        #pragma unroll
        for (int k=0;k<4;++k){
            double v = xs[k];
            double cl = fmin(fmax(v, -3.0), 3.0);
            double c  = cl / 3.0;
            double enc = copysign(log1p(fabs(c)*50.0) * INVD, c);
            double scaled = (enc + 1.0) * 7.5;
            int bq = (int)rint(scaled);
            bq = max(0, min(15, bq));
            float qk = g_dec[bq];
            r0 = __fmaf_rn(qk, g_DnT[idxs[k]*64 + lane],      r0);
            r1 = __fmaf_rn(qk, g_DnT[idxs[k]*64 + lane + 32], r1);
        }
        float d0 = __fsub_rn(r0, x0), d1 = __fsub_rn(r1, x1);
        out[(size_t)b*262144 + (size_t)lane*4096 + sp]      = __fadd_rn(x0, d0);
        out[(size_t)b*262144 + (size_t)(lane+32)*4096 + sp] = __fadd_rn(x1, d1);
        float ls = __fmaf_rn(d0, d0, __fmul_rn(d1, d1));
        #pragma unroll
        for (int off=16; off>0; off>>=1) ls += __shfl_down_sync(0xffffffffu, ls, off);
        if (lane == 0) g_fixloss[gsig] = ls;
        __syncwarp();
    }
}

// ---------------- deterministic parallel fixloss reduction ----------------
__global__ void k_fixred(){
    __shared__ float red[256];
    int base = blockIdx.x * 256;
    red[threadIdx.x] = g_fixloss[base + threadIdx.x];
    __syncthreads();
    for (int o = 128; o > 0; o >>= 1){
        if (threadIdx.x < o) red[threadIdx.x] += red[threadIdx.x + o];
        __syncthreads();
    }
    if (threadIdx.x == 0) g_partial2[blockIdx.x] = red[0];
}

// ---------------- finalize ----------------
__global__ void k_final(float* __restrict__ out, int out_size){
    __shared__ float red[256];
    float s = 0.f;
    for (int i = threadIdx.x; i < NBLOCKS; i += 256) s += g_partial[i];
    for (int i = threadIdx.x; i < 512; i += 256) s += g_partial2[i];
    red[threadIdx.x] = s;
    __syncthreads();
    for (int o = 128; o > 0; o >>= 1){
        if (threadIdx.x < o) red[threadIdx.x] += red[threadIdx.x + o];
        __syncthreads();
    }
    if (threadIdx.x == 0 && out_size > NELEM)
        out[NELEM] = 1.25f * red[0] / (float)NELEM;
}

// ---------------- launch ----------------
extern "C" void kernel_launch(void* const* d_in, const int* in_sizes, int n_in,
                              void* d_out, int out_size){
    const float* z_e  = (const float*)d_in[0];
    const float* dict = (const float*)d_in[1];
    float* out = (float*)d_out;

    cudaFuncSetAttribute(k_main, cudaFuncAttributeMaxDynamicSharedMemorySize, SM_BYTES);

    k_normalize<<<16, 256>>>(dict);
    k_gram<<<256, 256>>>();
    k_main<<<NBLOCKS, 512, SM_BYTES>>>(z_e, out);
    k_fix<<<296, 256>>>(z_e, out);
    k_fixred<<<512, 256>>>();
    k_final<<<1, 256>>>(out, out_size);
}